// round 1
// baseline (speedup 1.0000x reference)
#include <cuda_runtime.h>

#define N_NODES 50000
#define E_EDGES 800000

// ---------------- static scratch (no allocs allowed) ----------------
__device__ float g_agg0[N_NODES * 64];
__device__ float g_buf1[N_NODES * 512];
__device__ float g_buf2[N_NODES * 512];
__device__ float g_agg1[N_NODES * 512];
__device__ float g_t128[N_NODES * 128];
__device__ int   g_is64;

// Detect whether edge_index is int64 or int32 on device (graph-capture safe).
// If the buffer holds int32 indices in [0, 50000), reading pairs as u64 gives
// values >= 2^32 unless the high half happens to be 0 (P ~ (1/50000)^16 for
// all 16 probes) — so "all 16 u64 probes < N" <=> genuinely int64.
__global__ void detect_idx_kernel(const unsigned long long* ei) {
    if (blockIdx.x == 0 && threadIdx.x == 0) {
        int ok = 1;
        #pragma unroll
        for (int i = 0; i < 16; i++) {
            if (ei[i] >= (unsigned long long)N_NODES) ok = 0;
        }
        g_is64 = ok;
    }
}

__global__ void copy_f4_kernel(float4* __restrict__ dst, const float4* __restrict__ src, int n4) {
    int i = blockIdx.x * blockDim.x + threadIdx.x;
    if (i < n4) dst[i] = src[i];
}

// scatter-add: out[dst[e]] += feat[src[e]] for D-dim features, float4 per thread
template <int D>
__global__ void scatter_add_kernel(float* __restrict__ out, const float* __restrict__ feat,
                                   const void* __restrict__ ei_raw) {
    const int D4 = D / 4;
    long long t = (long long)blockIdx.x * blockDim.x + threadIdx.x;
    if (t >= (long long)E_EDGES * D4) return;
    int e  = (int)(t / D4);
    int d4 = (int)(t % D4);
    long long s, d;
    if (g_is64) {
        const long long* p = (const long long*)ei_raw;
        s = p[e]; d = p[E_EDGES + e];
    } else {
        const int* p = (const int*)ei_raw;
        s = p[e]; d = p[E_EDGES + e];
    }
    float4 v = *(const float4*)(feat + s * (long long)D + d4 * 4);
    float* o = out + d * (long long)D + d4 * 4;
    atomicAdd(o + 0, v.x);
    atomicAdd(o + 1, v.y);
    atomicAdd(o + 2, v.z);
    atomicAdd(o + 3, v.w);
}

// ---------------- fused GEMM + bias + activation ----------------
// C[M, Nn] = act(A[M, K] @ W[Nn, K]^T + bias)
// ACT: 0 = none, 1 = leaky_relu(0.1), 2 = relu
// Requirements: Nn % 128 == 0, K % 16 == 0 (holds for all layers here).
#define BM 128
#define BN 128
#define BK 16

template <int ACT>
__global__ __launch_bounds__(256) void gemm_bias_act_kernel(
    const float* __restrict__ A, const float* __restrict__ W,
    const float* __restrict__ bias, float* __restrict__ C,
    int M, int Nn, int K)
{
    __shared__ float As[BK][BM];
    __shared__ float Ws[BK][BN];

    const int tid = threadIdx.x;
    const int tx = tid & 15;   // 16 col-groups of 8
    const int ty = tid >> 4;   // 16 row-groups of 8
    const int m0 = blockIdx.y * BM;
    const int n0 = blockIdx.x * BN;

    float acc[8][8] = {};

    for (int k0 = 0; k0 < K; k0 += BK) {
        // cooperative loads: 128 rows x 16 k each for A and W (K-contiguous -> float4)
        #pragma unroll
        for (int l = 0; l < 2; l++) {
            int idx = tid + l * 256;       // 0..511
            int row = idx >> 2;            // 0..127
            int kq  = idx & 3;             // float4 slot within BK
            int ar = m0 + row;
            float4 v = make_float4(0.f, 0.f, 0.f, 0.f);
            if (ar < M) v = *(const float4*)&A[(long long)ar * K + k0 + kq * 4];
            As[kq * 4 + 0][row] = v.x;
            As[kq * 4 + 1][row] = v.y;
            As[kq * 4 + 2][row] = v.z;
            As[kq * 4 + 3][row] = v.w;
            int wr = n0 + row;             // Nn % 128 == 0 -> always in range
            float4 w = *(const float4*)&W[(long long)wr * K + k0 + kq * 4];
            Ws[kq * 4 + 0][row] = w.x;
            Ws[kq * 4 + 1][row] = w.y;
            Ws[kq * 4 + 2][row] = w.z;
            Ws[kq * 4 + 3][row] = w.w;
        }
        __syncthreads();

        #pragma unroll
        for (int kk = 0; kk < BK; kk++) {
            float4 a0 = *(const float4*)&As[kk][ty * 8];
            float4 a1 = *(const float4*)&As[kk][ty * 8 + 4];
            float4 b0 = *(const float4*)&Ws[kk][tx * 8];
            float4 b1 = *(const float4*)&Ws[kk][tx * 8 + 4];
            float a[8] = {a0.x, a0.y, a0.z, a0.w, a1.x, a1.y, a1.z, a1.w};
            float b[8] = {b0.x, b0.y, b0.z, b0.w, b1.x, b1.y, b1.z, b1.w};
            #pragma unroll
            for (int i = 0; i < 8; i++)
                #pragma unroll
                for (int j = 0; j < 8; j++)
                    acc[i][j] += a[i] * b[j];
        }
        __syncthreads();
    }

    #pragma unroll
    for (int i = 0; i < 8; i++) {
        int row = m0 + ty * 8 + i;
        if (row >= M) break;
        #pragma unroll
        for (int j = 0; j < 8; j++) {
            int col = n0 + tx * 8 + j;
            float v = acc[i][j] + bias[col];
            if (ACT == 1) v = (v > 0.f) ? v : 0.1f * v;
            else if (ACT == 2) v = (v > 0.f) ? v : 0.f;
            C[(long long)row * Nn + col] = v;
        }
    }
}

// ---------------- launch ----------------
extern "C" void kernel_launch(void* const* d_in, const int* in_sizes, int n_in,
                              void* d_out, int out_size) {
    const float* x    = (const float*)d_in[0];
    const void*  ei   = d_in[1];
    const float* W_s1 = (const float*)d_in[2];
    const float* b_s1 = (const float*)d_in[3];
    const float* W_s2 = (const float*)d_in[4];
    const float* b_s2 = (const float*)d_in[5];
    const float* W_s3 = (const float*)d_in[6];
    const float* b_s3 = (const float*)d_in[7];
    const float* W_s4 = (const float*)d_in[8];
    const float* b_s4 = (const float*)d_in[9];
    const float* W_m1 = (const float*)d_in[10];
    const float* b_m1 = (const float*)d_in[11];
    const float* W_m2 = (const float*)d_in[12];
    const float* b_m2 = (const float*)d_in[13];
    const float* W_l1 = (const float*)d_in[14];
    const float* b_l1 = (const float*)d_in[15];
    const float* W_l2 = (const float*)d_in[16];
    const float* b_l2 = (const float*)d_in[17];
    float* out = (float*)d_out;

    float *agg0, *buf1, *buf2, *agg1, *t128;
    cudaGetSymbolAddress((void**)&agg0, g_agg0);
    cudaGetSymbolAddress((void**)&buf1, g_buf1);
    cudaGetSymbolAddress((void**)&buf2, g_buf2);
    cudaGetSymbolAddress((void**)&agg1, g_agg1);
    cudaGetSymbolAddress((void**)&t128, g_t128);

    const int M = N_NODES;

    detect_idx_kernel<<<1, 32>>>((const unsigned long long*)ei);

    // agg0 = x + scatter_add(x)
    {
        int n4 = N_NODES * 64 / 4;
        copy_f4_kernel<<<(n4 + 255) / 256, 256>>>((float4*)agg0, (const float4*)x, n4);
        long long th = (long long)E_EDGES * (64 / 4);
        scatter_add_kernel<64><<<(int)((th + 255) / 256), 256>>>(agg0, x, ei);
    }

    // shared MLP: 64 -> 512 -> 512 -> 512 -> 512, then outer relu fused into last layer
    gemm_bias_act_kernel<1><<<dim3(512 / BN, (M + BM - 1) / BM), 256>>>(agg0, W_s1, b_s1, buf1, M, 512, 64);
    gemm_bias_act_kernel<1><<<dim3(512 / BN, (M + BM - 1) / BM), 256>>>(buf1, W_s2, b_s2, buf2, M, 512, 512);
    gemm_bias_act_kernel<1><<<dim3(512 / BN, (M + BM - 1) / BM), 256>>>(buf2, W_s3, b_s3, buf1, M, 512, 512);
    gemm_bias_act_kernel<2><<<dim3(512 / BN, (M + BM - 1) / BM), 256>>>(buf1, W_s4, b_s4, buf2, M, 512, 512);

    // agg1 = h + scatter_add(h)   (h = buf2)
    {
        int n4 = N_NODES * 512 / 4;
        copy_f4_kernel<<<(n4 + 255) / 256, 256>>>((float4*)agg1, (const float4*)buf2, n4);
        long long th = (long long)E_EDGES * (512 / 4);
        scatter_add_kernel<512><<<(int)((th + 255) / 256), 256>>>(agg1, buf2, ei);
    }

    // mu head: relu(agg1 @ W_m1^T + b_m1) @ W_m2^T + b_m2
    gemm_bias_act_kernel<2><<<dim3(128 / BN, (M + BM - 1) / BM), 256>>>(agg1, W_m1, b_m1, t128, M, 128, 512);
    gemm_bias_act_kernel<0><<<dim3(128 / BN, (M + BM - 1) / BM), 256>>>(t128, W_m2, b_m2, out, M, 128, 128);

    // logvar head
    gemm_bias_act_kernel<2><<<dim3(128 / BN, (M + BM - 1) / BM), 256>>>(agg1, W_l1, b_l1, t128, M, 128, 512);
    gemm_bias_act_kernel<0><<<dim3(128 / BN, (M + BM - 1) / BM), 256>>>(t128, W_l2, b_l2, out + (long long)N_NODES * 128, M, 128, 128);

    (void)in_sizes; (void)n_in; (void)out_size;
}

// round 2
// speedup vs baseline: 1.5459x; 1.5459x over previous
#include <cuda_runtime.h>

#define N_NODES 50000
#define E_EDGES 800000

// ---------------- static scratch (no allocs allowed) ----------------
__device__ float g_agg0[N_NODES * 64];
__device__ float g_buf1[N_NODES * 512];
__device__ float g_buf2[N_NODES * 512];
__device__ float g_agg1[N_NODES * 512];   // reused as agg256 (first 256 cols)
__device__ int   g_is64;

// Detect whether edge_index is int64 or int32 on device (graph-capture safe).
__global__ void detect_idx_kernel(const unsigned long long* ei) {
    if (blockIdx.x == 0 && threadIdx.x == 0) {
        int ok = 1;
        #pragma unroll
        for (int i = 0; i < 16; i++) {
            if (ei[i] >= (unsigned long long)N_NODES) ok = 0;
        }
        g_is64 = ok;
    }
}

__global__ void copy_f4_kernel(float4* __restrict__ dst, const float4* __restrict__ src, int n4) {
    int i = blockIdx.x * blockDim.x + threadIdx.x;
    if (i < n4) dst[i] = src[i];
}

// vector reduction: out[0..3] += v  (no return, L2-side atomic)
__device__ __forceinline__ void red_add_v4(float* addr, float4 v) {
    asm volatile("red.global.add.v4.f32 [%0], {%1, %2, %3, %4};"
                 :: "l"(addr), "f"(v.x), "f"(v.y), "f"(v.z), "f"(v.w) : "memory");
}

// scatter-add: out[dst[e]] += feat[src[e]], D floats per row (D4 = D/4 float4s, power of 2)
template <int D4>
__global__ void scatter_add_kernel(float* __restrict__ out, const float* __restrict__ feat,
                                   const void* __restrict__ ei_raw) {
    long long t = (long long)blockIdx.x * blockDim.x + threadIdx.x;
    if (t >= (long long)E_EDGES * D4) return;
    int e = (int)(t / D4);
    int c = (int)(t & (D4 - 1));
    long long s, d;
    if (g_is64) {
        const long long* p = (const long long*)ei_raw;
        s = __ldg(p + e); d = __ldg(p + E_EDGES + e);
    } else {
        const int* p = (const int*)ei_raw;
        s = __ldg(p + e); d = __ldg(p + E_EDGES + e);
    }
    float4 v = __ldg((const float4*)feat + s * D4 + c);
    red_add_v4(out + (d * D4 + c) * 4, v);
}

// ---------------- packed-FFMA2 GEMM + fused epilogue/prologue ----------------
// C[M,Nn] = act(A'[M,K] @ W[Nn,K]^T (+ bias))
//   A'[r,k] = INREL ? relu(A[r*lda+k] + abias[k]) : A[r*lda+k]
//   TWOW: W row n -> (n<128 ? W0[n] : W1[n-128])
//   DUAL: also store C2 (same layout)
// ACT: 0 none, 1 leaky_relu(0.1), 2 relu. Requires Nn%128==0, K%16==0.
#define BM 128
#define BN 128
#define BK 16
#define BMP 132   // padded row length in smem

__device__ __forceinline__ unsigned long long pack2(float x, float y) {
    unsigned long long r;
    asm("mov.b64 %0, {%1, %2};" : "=l"(r) : "f"(x), "f"(y));
    return r;
}
__device__ __forceinline__ void fma2(unsigned long long& d, unsigned long long a, unsigned long long b) {
    asm("fma.rn.f32x2 %0, %1, %2, %0;" : "+l"(d) : "l"(a), "l"(b));
}
__device__ __forceinline__ float2 unpack2(unsigned long long v) {
    float2 f;
    asm("mov.b64 {%0, %1}, %2;" : "=f"(f.x), "=f"(f.y) : "l"(v));
    return f;
}

template <int ACT, bool INREL, bool DUAL, bool TWOW, bool HASB>
__global__ __launch_bounds__(256, 2) void gemm_kernel(
    const float* __restrict__ A, int lda, const float* __restrict__ abias,
    const float* __restrict__ W0, const float* __restrict__ W1,
    const float* __restrict__ bias,
    float* __restrict__ C, float* __restrict__ C2,
    int M, int Nn, int K)
{
    __shared__ float As[2][BK][BMP];
    __shared__ float Ws[2][BK][BMP];

    const int tid = threadIdx.x;
    const int tx = tid & 15;
    const int ty = tid >> 4;
    const int m0 = blockIdx.y * BM;
    const int n0 = blockIdx.x * BN;

    // staging slot geometry: 512 slots, 2 per thread
    const int row0 = (tid + 0)   >> 2, kq0 = (tid + 0)   & 3;
    const int row1 = (tid + 256) >> 2, kq1 = (tid + 256) & 3;

    unsigned long long acc[8][4] = {};
    float4 av[2], wv[2];

    auto load_tile = [&](int k0) {
        #pragma unroll
        for (int l = 0; l < 2; l++) {
            const int row = l ? row1 : row0;
            const int kq  = l ? kq1 : kq0;
            const int r = m0 + row;
            float4 v = make_float4(0.f, 0.f, 0.f, 0.f);
            if (r < M) {
                v = __ldg((const float4*)&A[(size_t)r * lda + k0 + kq * 4]);
                if (INREL) {
                    float4 ab = __ldg((const float4*)&abias[k0 + kq * 4]);
                    v.x = fmaxf(v.x + ab.x, 0.f);
                    v.y = fmaxf(v.y + ab.y, 0.f);
                    v.z = fmaxf(v.z + ab.z, 0.f);
                    v.w = fmaxf(v.w + ab.w, 0.f);
                }
            }
            av[l] = v;
            const int wr = n0 + row;
            const float* Wp;
            if (TWOW) Wp = (wr < 128) ? (W0 + (size_t)wr * K) : (W1 + (size_t)(wr - 128) * K);
            else      Wp = W0 + (size_t)wr * K;
            wv[l] = __ldg((const float4*)&Wp[k0 + kq * 4]);
        }
    };

    auto store_tile = [&](int buf) {
        #pragma unroll
        for (int l = 0; l < 2; l++) {
            const int row = l ? row1 : row0;
            const int kq  = l ? kq1 : kq0;
            As[buf][kq * 4 + 0][row] = av[l].x;
            As[buf][kq * 4 + 1][row] = av[l].y;
            As[buf][kq * 4 + 2][row] = av[l].z;
            As[buf][kq * 4 + 3][row] = av[l].w;
            Ws[buf][kq * 4 + 0][row] = wv[l].x;
            Ws[buf][kq * 4 + 1][row] = wv[l].y;
            Ws[buf][kq * 4 + 2][row] = wv[l].z;
            Ws[buf][kq * 4 + 3][row] = wv[l].w;
        }
    };

    auto compute = [&](int buf) {
        #pragma unroll
        for (int kk = 0; kk < BK; kk++) {
            float4 a0 = *(const float4*)&As[buf][kk][ty * 8];
            float4 a1 = *(const float4*)&As[buf][kk][ty * 8 + 4];
            float4 w0 = *(const float4*)&Ws[buf][kk][tx * 8];
            float4 w1 = *(const float4*)&Ws[buf][kk][tx * 8 + 4];
            unsigned long long bb[4] = { pack2(w0.x, w0.y), pack2(w0.z, w0.w),
                                         pack2(w1.x, w1.y), pack2(w1.z, w1.w) };
            float aarr[8] = {a0.x, a0.y, a0.z, a0.w, a1.x, a1.y, a1.z, a1.w};
            #pragma unroll
            for (int i = 0; i < 8; i++) {
                unsigned long long aa = pack2(aarr[i], aarr[i]);
                #pragma unroll
                for (int j = 0; j < 4; j++) fma2(acc[i][j], aa, bb[j]);
            }
        }
    };

    // prologue
    load_tile(0);
    store_tile(0);
    __syncthreads();

    const int nk = K / BK;
    int buf = 0;
    for (int it = 1; it < nk; it++) {
        load_tile(it * BK);    // issue global loads
        compute(buf);          // overlap their latency
        store_tile(buf ^ 1);   // safe: other buffer, prior readers synced last iter
        __syncthreads();
        buf ^= 1;
    }
    compute(buf);

    // epilogue
    #pragma unroll
    for (int i = 0; i < 8; i++) {
        const int row = m0 + ty * 8 + i;
        if (row >= M) break;
        float o[8];
        #pragma unroll
        for (int j = 0; j < 4; j++) {
            float2 v = unpack2(acc[i][j]);
            o[2 * j] = v.x; o[2 * j + 1] = v.y;
        }
        const int col0 = n0 + tx * 8;
        #pragma unroll
        for (int j = 0; j < 8; j++) {
            float v = o[j];
            if (HASB) v += bias[col0 + j];
            if (ACT == 1) v = (v > 0.f) ? v : 0.1f * v;
            else if (ACT == 2) v = (v > 0.f) ? v : 0.f;
            o[j] = v;
        }
        float4 v0 = make_float4(o[0], o[1], o[2], o[3]);
        float4 v1 = make_float4(o[4], o[5], o[6], o[7]);
        *(float4*)&C[(size_t)row * Nn + col0]     = v0;
        *(float4*)&C[(size_t)row * Nn + col0 + 4] = v1;
        if (DUAL) {
            *(float4*)&C2[(size_t)row * Nn + col0]     = v0;
            *(float4*)&C2[(size_t)row * Nn + col0 + 4] = v1;
        }
    }
}

// ---------------- launch ----------------
extern "C" void kernel_launch(void* const* d_in, const int* in_sizes, int n_in,
                              void* d_out, int out_size) {
    const float* x    = (const float*)d_in[0];
    const void*  ei   = d_in[1];
    const float* W_s1 = (const float*)d_in[2];
    const float* b_s1 = (const float*)d_in[3];
    const float* W_s2 = (const float*)d_in[4];
    const float* b_s2 = (const float*)d_in[5];
    const float* W_s3 = (const float*)d_in[6];
    const float* b_s3 = (const float*)d_in[7];
    const float* W_s4 = (const float*)d_in[8];
    const float* b_s4 = (const float*)d_in[9];
    const float* W_m1 = (const float*)d_in[10];
    const float* b_m1 = (const float*)d_in[11];
    const float* W_m2 = (const float*)d_in[12];
    const float* b_m2 = (const float*)d_in[13];
    const float* W_l1 = (const float*)d_in[14];
    const float* b_l1 = (const float*)d_in[15];
    const float* W_l2 = (const float*)d_in[16];
    const float* b_l2 = (const float*)d_in[17];
    float* out = (float*)d_out;

    float *agg0, *buf1, *buf2, *agg256;
    cudaGetSymbolAddress((void**)&agg0,   g_agg0);
    cudaGetSymbolAddress((void**)&buf1,   g_buf1);
    cudaGetSymbolAddress((void**)&buf2,   g_buf2);
    cudaGetSymbolAddress((void**)&agg256, g_agg1);
    float* t256 = buf1;   // safe reuse: s4 (reader of buf1) completes before cat writes it

    const int M = N_NODES;
    const dim3 blk(256);
    const dim3 g512(4, (M + BM - 1) / BM);
    const dim3 g256(2, (M + BM - 1) / BM);
    const dim3 g128(1, (M + BM - 1) / BM);

    detect_idx_kernel<<<1, 32>>>((const unsigned long long*)ei);

    // agg0 = x + A·x   (64-dim)
    {
        int n4 = N_NODES * 64 / 4;
        copy_f4_kernel<<<(n4 + 255) / 256, 256>>>((float4*)agg0, (const float4*)x, n4);
        long long th = (long long)E_EDGES * 16;
        scatter_add_kernel<16><<<(int)((th + 255) / 256), 256>>>(agg0, x, ei);
    }

    // shared MLP (64 -> 512 -> 512 -> 512 -> 512), outer relu fused into s4
    gemm_kernel<1, false, false, false, true><<<g512, blk>>>(agg0, 64,  nullptr, W_s1, nullptr, b_s1, buf1, nullptr, M, 512, 64);
    gemm_kernel<1, false, false, false, true><<<g512, blk>>>(buf1, 512, nullptr, W_s2, nullptr, b_s2, buf2, nullptr, M, 512, 512);
    gemm_kernel<1, false, false, false, true><<<g512, blk>>>(buf2, 512, nullptr, W_s3, nullptr, b_s3, buf1, nullptr, M, 512, 512);
    gemm_kernel<2, false, false, false, true><<<g512, blk>>>(buf1, 512, nullptr, W_s4, nullptr, b_s4, buf2, nullptr, M, 512, 512);

    // t256 = h @ [W_m1; W_l1]^T  (no bias); agg256 initialized to t256 via dual store.
    // Aggregation commutes with the linear map: (I+A)h @ W^T = (I+A)(h @ W^T).
    gemm_kernel<0, false, true, true, false><<<g256, blk>>>(buf2, 512, nullptr, W_m1, W_l1, nullptr, t256, agg256, M, 256, 512);

    // agg256 += A·t256   (256-dim instead of 512-dim: half the scatter traffic)
    {
        long long th = (long long)E_EDGES * 64;
        scatter_add_kernel<64><<<(int)((th + 255) / 256), 256>>>(agg256, t256, ei);
    }

    // heads: bias+relu fused into the A operand load
    gemm_kernel<0, true, false, false, true><<<g128, blk>>>(agg256,       256, b_m1, W_m2, nullptr, b_m2, out,                          nullptr, M, 128, 128);
    gemm_kernel<0, true, false, false, true><<<g128, blk>>>(agg256 + 128, 256, b_l1, W_l2, nullptr, b_l2, out + (size_t)N_NODES * 128, nullptr, M, 128, 128);

    (void)in_sizes; (void)n_in; (void)out_size;
}

// round 4
// speedup vs baseline: 3.4005x; 2.1997x over previous
#include <cuda_runtime.h>
#include <cuda_bf16.h>
#include <cstdint>

#define N_NODES 50000
#define E_EDGES 800000

// ---------------- static scratch (no allocs allowed) ----------------
__device__ float g_agg0[N_NODES * 64];
__device__ float g_t256[N_NODES * 256];
__device__ float g_agg256[N_NODES * 256];
__device__ __nv_bfloat16 g_ah[N_NODES * 512];
__device__ __nv_bfloat16 g_al[N_NODES * 512];
__device__ __nv_bfloat16 g_bh[N_NODES * 512];
__device__ __nv_bfloat16 g_bl[N_NODES * 512];
#define W_TOTAL 983040
__device__ __nv_bfloat16 g_wh[W_TOTAL];
__device__ __nv_bfloat16 g_wl[W_TOTAL];
__device__ int g_is64;

// weight pack offsets (elements)
#define OFF_S1  0
#define OFF_S2  32768
#define OFF_S3  294912
#define OFF_S4  557056
#define OFF_CAT 819200
#define OFF_M2  950272
#define OFF_L2  966656

__device__ __forceinline__ uint32_t smem_u32(const void* p) {
    uint32_t a;
    asm("{ .reg .u64 t; cvta.to.shared.u64 t, %1; cvt.u32.u64 %0, t; }" : "=r"(a) : "l"(p));
    return a;
}

#define SW128(o) ((o) ^ (((o) >> 3) & 0x70))

// ---------------- misc kernels ----------------
__global__ void detect_idx_kernel(const unsigned long long* ei) {
    if (blockIdx.x == 0 && threadIdx.x == 0) {
        int ok = 1;
        #pragma unroll
        for (int i = 0; i < 16; i++)
            if (ei[i] >= (unsigned long long)N_NODES) ok = 0;
        g_is64 = ok;
    }
}

__global__ void copy_f4_kernel(float4* __restrict__ dst, const float4* __restrict__ src, int n4) {
    int i = blockIdx.x * blockDim.x + threadIdx.x;
    if (i < n4) dst[i] = src[i];
}

__device__ __forceinline__ void red_add_v4(float* addr, float4 v) {
    asm volatile("red.global.add.v4.f32 [%0], {%1, %2, %3, %4};"
                 :: "l"(addr), "f"(v.x), "f"(v.y), "f"(v.z), "f"(v.w) : "memory");
}

template <int D4>
__global__ void scatter_add_kernel(float* __restrict__ out, const float* __restrict__ feat,
                                   const void* __restrict__ ei_raw) {
    long long t = (long long)blockIdx.x * blockDim.x + threadIdx.x;
    if (t >= (long long)E_EDGES * D4) return;
    int e = (int)(t / D4);
    int c = (int)(t & (D4 - 1));
    long long s, d;
    if (g_is64) {
        const long long* p = (const long long*)ei_raw;
        s = __ldg(p + e); d = __ldg(p + E_EDGES + e);
    } else {
        const int* p = (const int*)ei_raw;
        s = __ldg(p + e); d = __ldg(p + E_EDGES + e);
    }
    float4 v = __ldg((const float4*)feat + s * D4 + c);
    red_add_v4(out + (d * D4 + c) * 4, v);
}

// fp32 -> (hi, lo) bf16 split
__global__ void split2_kernel(const float2* __restrict__ src,
                              __nv_bfloat162* __restrict__ hi, __nv_bfloat162* __restrict__ lo, int n2) {
    int i = blockIdx.x * blockDim.x + threadIdx.x;
    if (i >= n2) return;
    float2 v = src[i];
    __nv_bfloat16 h0 = __float2bfloat16(v.x), h1 = __float2bfloat16(v.y);
    __nv_bfloat16 l0 = __float2bfloat16(v.x - __bfloat162float(h0));
    __nv_bfloat16 l1 = __float2bfloat16(v.y - __bfloat162float(h1));
    hi[i] = __nv_bfloat162(h0, h1);
    lo[i] = __nv_bfloat162(l0, l1);
}

// head input: relu(agg[:, coff:coff+128] + bias) -> hi/lo bf16 [M,128]
__global__ void split_head_kernel(const float* __restrict__ agg, const float* __restrict__ bias,
                                  int coff, __nv_bfloat16* __restrict__ hi, __nv_bfloat16* __restrict__ lo) {
    int i = blockIdx.x * blockDim.x + threadIdx.x;
    if (i >= N_NODES * 128) return;
    int r = i >> 7, c = i & 127;
    float v = fmaxf(agg[r * 256 + coff + c] + __ldg(bias + c), 0.f);
    __nv_bfloat16 h = __float2bfloat16(v);
    hi[i] = h;
    lo[i] = __float2bfloat16(v - __bfloat162float(h));
}

// ---------------- mma.sync split-bf16 GEMM ----------------
// C[M,Nn] = act(A[M,K] @ W[Nn,K]^T + bias); A=Ah+Al, W=Wh+Wl bf16 splits.
// Computed as Ah*Wh + Ah*Wl + Al*Wh, fp32 accum via mma.sync.m16n8k16.bf16.
// CTA tile 128x128, 8 warps of 64x32, K staged in 64-elem SW128 chunks,
// cp.async double buffer (2 x 64KB smem).
#define GT 256
#define SMEM_GEMM 131072

#define LDSM4(r0, r1, r2, r3, a) \
    asm volatile("ldmatrix.sync.aligned.m8n8.x4.shared.b16 {%0,%1,%2,%3}, [%4];" \
                 : "=r"(r0), "=r"(r1), "=r"(r2), "=r"(r3) : "r"(a))

#define HMMA(c, a0, a1, a2, a3, b0, b1) \
    asm volatile("mma.sync.aligned.m16n8k16.row.col.f32.bf16.bf16.f32 " \
                 "{%0,%1,%2,%3}, {%4,%5,%6,%7}, {%8,%9}, {%0,%1,%2,%3};" \
                 : "+f"((c)[0]), "+f"((c)[1]), "+f"((c)[2]), "+f"((c)[3]) \
                 : "r"(a0), "r"(a1), "r"(a2), "r"(a3), "r"(b0), "r"(b1))

__device__ __forceinline__ void cp16(uint32_t saddr, const void* gptr, uint32_t sz) {
    asm volatile("cp.async.cg.shared.global [%0], [%1], 16, %2;"
                 :: "r"(saddr), "l"(gptr), "r"(sz) : "memory");
}
#define CP_COMMIT() asm volatile("cp.async.commit_group;" ::: "memory")
#define CP_WAIT(n)  asm volatile("cp.async.wait_group %0;" :: "n"(n) : "memory")

template <int ACT, bool EMITF, bool EMITB, bool DUAL, bool HASB>
__global__ __launch_bounds__(GT, 1)
void gemm_tc(const __nv_bfloat16* __restrict__ Ah, const __nv_bfloat16* __restrict__ Al, int lda,
             const __nv_bfloat16* __restrict__ Wh, const __nv_bfloat16* __restrict__ Wl,
             const float* __restrict__ bias,
             float* __restrict__ C, float* __restrict__ C2, int ldc,
             __nv_bfloat16* __restrict__ Ch, __nv_bfloat16* __restrict__ Cl, int ldcb,
             int M, int K)
{
    extern __shared__ char smem[];
    const uint32_t sb = smem_u32(smem);

    const int tid = threadIdx.x;
    const int wid = tid >> 5;
    const int lane = tid & 31;
    const int m0 = blockIdx.y * 128;
    const int n0 = blockIdx.x * 128;
    const int wm = (wid & 1) * 64;
    const int wn = (wid >> 1) * 32;

    float acc[4][4][4] = {};

    // staging geometry: per tile 1024 16B-groups; this thread covers 4 rows/tile
    const int srow = tid >> 3, sg = tid & 7;
    const uint32_t s_off = SW128((uint32_t)(srow * 128 + sg * 16));

    auto stage = [&](int buf, int k0) {
        const uint32_t tb = sb + buf * 65536;
        #pragma unroll
        for (int t = 0; t < 4; t++) {
            const int row = srow + t * 32;
            const uint32_t so = SW128((uint32_t)(row * 128 + sg * 16));
            const int ar = m0 + row;
            const int ok = (ar < M);
            const size_t ao = (size_t)(ok ? ar : 0) * lda + k0 + sg * 8;
            cp16(tb + 0     + so, Ah + ao, ok ? 16 : 0);
            cp16(tb + 16384 + so, Al + ao, ok ? 16 : 0);
            const size_t wo = (size_t)(n0 + row) * K + k0 + sg * 8;
            cp16(tb + 32768 + so, Wh + wo, 16);
            cp16(tb + 49152 + so, Wl + wo, 16);
        }
        CP_COMMIT();
    };

    // ldmatrix per-lane address components
    const int o = lane >> 3, r = lane & 7;
    // A: matrix o -> (rows o&1 ? 8-15 : 0-7, k o>>1 ? hi : lo)
    int aRow[4];
    #pragma unroll
    for (int i = 0; i < 4; i++) aRow[i] = (wm + 16 * i + (o & 1) * 8 + r) * 128 + (o >> 1) * 16;
    // B (W rows = output cols): matrix o -> (n o>>1 ? sub+1 : sub, k o&1 ? hi : lo)
    int bRow[2];
    #pragma unroll
    for (int p = 0; p < 2; p++) bRow[p] = (wn + p * 16 + (o >> 1) * 8 + r) * 128 + (o & 1) * 16;

    const int nchunks = K >> 6;
    stage(0, 0);
    for (int c = 0; c < nchunks; c++) {
        if (c + 1 < nchunks) stage((c + 1) & 1, (c + 1) << 6);
        if (c + 1 < nchunks) { CP_WAIT(1); } else { CP_WAIT(0); }
        __syncthreads();

        const uint32_t tb = sb + (c & 1) * 65536;
        #pragma unroll
        for (int ks = 0; ks < 4; ks++) {
            const int kb = ks * 32;
            uint32_t ah[4][4], al[4][4], wh[2][4], wl[2][4];
            #pragma unroll
            for (int i = 0; i < 4; i++) {
                const uint32_t ad = SW128((uint32_t)(aRow[i] + kb));
                LDSM4(ah[i][0], ah[i][1], ah[i][2], ah[i][3], tb + ad);
                LDSM4(al[i][0], al[i][1], al[i][2], al[i][3], tb + 16384 + ad);
            }
            #pragma unroll
            for (int p = 0; p < 2; p++) {
                const uint32_t bd = SW128((uint32_t)(bRow[p] + kb));
                LDSM4(wh[p][0], wh[p][1], wh[p][2], wh[p][3], tb + 32768 + bd);
                LDSM4(wl[p][0], wl[p][1], wl[p][2], wl[p][3], tb + 49152 + bd);
            }
            #pragma unroll
            for (int i = 0; i < 4; i++) {
                #pragma unroll
                for (int j = 0; j < 4; j++) {
                    const uint32_t bh0 = wh[j >> 1][(j & 1) * 2], bh1 = wh[j >> 1][(j & 1) * 2 + 1];
                    const uint32_t bl0 = wl[j >> 1][(j & 1) * 2], bl1 = wl[j >> 1][(j & 1) * 2 + 1];
                    HMMA(acc[i][j], ah[i][0], ah[i][1], ah[i][2], ah[i][3], bh0, bh1);
                    HMMA(acc[i][j], ah[i][0], ah[i][1], ah[i][2], ah[i][3], bl0, bl1);
                    HMMA(acc[i][j], al[i][0], al[i][1], al[i][2], al[i][3], bh0, bh1);
                }
            }
        }
        __syncthreads();
    }

    // epilogue: d-frag (gid,2tig),(gid,2tig+1),(gid+8,..)
    const int gid = lane >> 2, tig = lane & 3;
    #pragma unroll
    for (int i = 0; i < 4; i++) {
        #pragma unroll
        for (int h = 0; h < 2; h++) {
            const int row = m0 + wm + 16 * i + 8 * h + gid;
            if (row >= M) continue;
            #pragma unroll
            for (int j = 0; j < 4; j++) {
                const int col = n0 + wn + 8 * j + 2 * tig;
                float v0 = acc[i][j][2 * h], v1 = acc[i][j][2 * h + 1];
                if (HASB) { v0 += __ldg(bias + col); v1 += __ldg(bias + col + 1); }
                if (ACT == 1) { v0 = (v0 > 0.f) ? v0 : 0.1f * v0; v1 = (v1 > 0.f) ? v1 : 0.1f * v1; }
                if (ACT == 2) { v0 = fmaxf(v0, 0.f); v1 = fmaxf(v1, 0.f); }
                if (EMITF) {
                    float2 fv = make_float2(v0, v1);
                    *(float2*)&C[(size_t)row * ldc + col] = fv;
                    if (DUAL) *(float2*)&C2[(size_t)row * ldc + col] = fv;
                }
                if (EMITB) {
                    __nv_bfloat16 h0 = __float2bfloat16(v0), h1 = __float2bfloat16(v1);
                    __nv_bfloat16 l0 = __float2bfloat16(v0 - __bfloat162float(h0));
                    __nv_bfloat16 l1 = __float2bfloat16(v1 - __bfloat162float(h1));
                    *(__nv_bfloat162*)&Ch[(size_t)row * ldcb + col] = __nv_bfloat162(h0, h1);
                    *(__nv_bfloat162*)&Cl[(size_t)row * ldcb + col] = __nv_bfloat162(l0, l1);
                }
            }
        }
    }
}

// ---------------- launch ----------------
extern "C" void kernel_launch(void* const* d_in, const int* in_sizes, int n_in,
                              void* d_out, int out_size) {
    const float* x    = (const float*)d_in[0];
    const void*  ei   = d_in[1];
    const float* W_s1 = (const float*)d_in[2];
    const float* b_s1 = (const float*)d_in[3];
    const float* W_s2 = (const float*)d_in[4];
    const float* b_s2 = (const float*)d_in[5];
    const float* W_s3 = (const float*)d_in[6];
    const float* b_s3 = (const float*)d_in[7];
    const float* W_s4 = (const float*)d_in[8];
    const float* b_s4 = (const float*)d_in[9];
    const float* W_m1 = (const float*)d_in[10];
    const float* b_m1 = (const float*)d_in[11];
    const float* W_m2 = (const float*)d_in[12];
    const float* b_m2 = (const float*)d_in[13];
    const float* W_l1 = (const float*)d_in[14];
    const float* b_l1 = (const float*)d_in[15];
    const float* W_l2 = (const float*)d_in[16];
    const float* b_l2 = (const float*)d_in[17];
    float* out = (float*)d_out;

    float *agg0, *t256, *agg256;
    __nv_bfloat16 *ah, *al, *bh, *bl, *wh, *wl;
    cudaGetSymbolAddress((void**)&agg0,   g_agg0);
    cudaGetSymbolAddress((void**)&t256,   g_t256);
    cudaGetSymbolAddress((void**)&agg256, g_agg256);
    cudaGetSymbolAddress((void**)&ah, g_ah);
    cudaGetSymbolAddress((void**)&al, g_al);
    cudaGetSymbolAddress((void**)&bh, g_bh);
    cudaGetSymbolAddress((void**)&bl, g_bl);
    cudaGetSymbolAddress((void**)&wh, g_wh);
    cudaGetSymbolAddress((void**)&wl, g_wl);

    static bool attr_done = false;
    if (!attr_done) {
        cudaFuncSetAttribute(gemm_tc<1, false, true,  false, true >, cudaFuncAttributeMaxDynamicSharedMemorySize, SMEM_GEMM);
        cudaFuncSetAttribute(gemm_tc<2, false, true,  false, true >, cudaFuncAttributeMaxDynamicSharedMemorySize, SMEM_GEMM);
        cudaFuncSetAttribute(gemm_tc<0, true,  false, true,  false>, cudaFuncAttributeMaxDynamicSharedMemorySize, SMEM_GEMM);
        cudaFuncSetAttribute(gemm_tc<0, true,  false, false, true >, cudaFuncAttributeMaxDynamicSharedMemorySize, SMEM_GEMM);
        attr_done = true;
    }

    const int M = N_NODES;
    const dim3 blk(GT);
    const dim3 g512(4, (M + 127) / 128);
    const dim3 g256(2, (M + 127) / 128);
    const dim3 g128(1, (M + 127) / 128);

    detect_idx_kernel<<<1, 32>>>((const unsigned long long*)ei);

    // ---- weight splits (fp32 -> hi/lo bf16, packed) ----
    split2_kernel<<<(512 * 64 / 2 + 255) / 256, 256>>>((const float2*)W_s1, (__nv_bfloat162*)(wh + OFF_S1), (__nv_bfloat162*)(wl + OFF_S1), 512 * 64 / 2);
    split2_kernel<<<(512 * 512 / 2 + 255) / 256, 256>>>((const float2*)W_s2, (__nv_bfloat162*)(wh + OFF_S2), (__nv_bfloat162*)(wl + OFF_S2), 512 * 512 / 2);
    split2_kernel<<<(512 * 512 / 2 + 255) / 256, 256>>>((const float2*)W_s3, (__nv_bfloat162*)(wh + OFF_S3), (__nv_bfloat162*)(wl + OFF_S3), 512 * 512 / 2);
    split2_kernel<<<(512 * 512 / 2 + 255) / 256, 256>>>((const float2*)W_s4, (__nv_bfloat162*)(wh + OFF_S4), (__nv_bfloat162*)(wl + OFF_S4), 512 * 512 / 2);
    split2_kernel<<<(128 * 512 / 2 + 255) / 256, 256>>>((const float2*)W_m1, (__nv_bfloat162*)(wh + OFF_CAT), (__nv_bfloat162*)(wl + OFF_CAT), 128 * 512 / 2);
    split2_kernel<<<(128 * 512 / 2 + 255) / 256, 256>>>((const float2*)W_l1, (__nv_bfloat162*)(wh + OFF_CAT + 65536), (__nv_bfloat162*)(wl + OFF_CAT + 65536), 128 * 512 / 2);
    split2_kernel<<<(128 * 128 / 2 + 255) / 256, 256>>>((const float2*)W_m2, (__nv_bfloat162*)(wh + OFF_M2), (__nv_bfloat162*)(wl + OFF_M2), 128 * 128 / 2);
    split2_kernel<<<(128 * 128 / 2 + 255) / 256, 256>>>((const float2*)W_l2, (__nv_bfloat162*)(wh + OFF_L2), (__nv_bfloat162*)(wl + OFF_L2), 128 * 128 / 2);

    // ---- agg0 = x + A.x (64-dim), then split ----
    {
        int n4 = N_NODES * 64 / 4;
        copy_f4_kernel<<<(n4 + 255) / 256, 256>>>((float4*)agg0, (const float4*)x, n4);
        long long th = (long long)E_EDGES * 16;
        scatter_add_kernel<16><<<(int)((th + 255) / 256), 256>>>(agg0, x, ei);
        split2_kernel<<<(N_NODES * 64 / 2 + 255) / 256, 256>>>((const float2*)agg0, (__nv_bfloat162*)ah, (__nv_bfloat162*)al, N_NODES * 64 / 2);
    }

    // ---- shared MLP, bf16-split outputs chained through epilogues ----
    gemm_tc<1, false, true, false, true><<<g512, blk, SMEM_GEMM>>>(ah, al, 64,  wh + OFF_S1, wl + OFF_S1, b_s1, nullptr, nullptr, 0, bh, bl, 512, M, 64);
    gemm_tc<1, false, true, false, true><<<g512, blk, SMEM_GEMM>>>(bh, bl, 512, wh + OFF_S2, wl + OFF_S2, b_s2, nullptr, nullptr, 0, ah, al, 512, M, 512);
    gemm_tc<1, false, true, false, true><<<g512, blk, SMEM_GEMM>>>(ah, al, 512, wh + OFF_S3, wl + OFF_S3, b_s3, nullptr, nullptr, 0, bh, bl, 512, M, 512);
    gemm_tc<2, false, true, false, true><<<g512, blk, SMEM_GEMM>>>(bh, bl, 512, wh + OFF_S4, wl + OFF_S4, b_s4, nullptr, nullptr, 0, ah, al, 512, M, 512);

    // ---- t256 = h @ [W_m1; W_l1]^T (no bias); dual store also inits agg256 = t256 ----
    gemm_tc<0, true, false, true, false><<<g256, blk, SMEM_GEMM>>>(ah, al, 512, wh + OFF_CAT, wl + OFF_CAT, nullptr, t256, agg256, 256, nullptr, nullptr, 0, M, 512);

    // ---- agg256 += A.t256 (aggregation commutes with the linear map) ----
    {
        long long th = (long long)E_EDGES * 64;
        scatter_add_kernel<64><<<(int)((th + 255) / 256), 256>>>(agg256, t256, ei);
    }

    // ---- head inputs: relu(agg256 + b) -> bf16 splits ----
    split_head_kernel<<<(N_NODES * 128 + 255) / 256, 256>>>(agg256, b_m1, 0,   bh, bl);
    split_head_kernel<<<(N_NODES * 128 + 255) / 256, 256>>>(agg256, b_l1, 128, bh + (size_t)N_NODES * 128, bl + (size_t)N_NODES * 128);

    // ---- heads ----
    gemm_tc<0, true, false, false, true><<<g128, blk, SMEM_GEMM>>>(bh, bl, 128, wh + OFF_M2, wl + OFF_M2, b_m2, out, nullptr, 128, nullptr, nullptr, 0, M, 128);
    gemm_tc<0, true, false, false, true><<<g128, blk, SMEM_GEMM>>>(bh + (size_t)N_NODES * 128, bl + (size_t)N_NODES * 128, 128, wh + OFF_L2, wl + OFF_L2, b_l2, out + (size_t)N_NODES * 128, nullptr, 128, nullptr, nullptr, 0, M, 128);

    (void)in_sizes; (void)n_in; (void)out_size;
}

// round 5
// speedup vs baseline: 4.0547x; 1.1924x over previous
#include <cuda_runtime.h>
#include <cuda_bf16.h>
#include <cstdint>

#define N_NODES 50000
#define E_EDGES 800000

// ---------------- static scratch (no allocs allowed) ----------------
__device__ float g_t256[N_NODES * 256];
__device__ __nv_bfloat16 g_ah[N_NODES * 512];
__device__ __nv_bfloat16 g_al[N_NODES * 512];
__device__ __nv_bfloat16 g_bh[N_NODES * 512];
__device__ __nv_bfloat16 g_bl[N_NODES * 512];
#define W_TOTAL 983040
__device__ __nv_bfloat16 g_wh[W_TOTAL];
__device__ __nv_bfloat16 g_wl[W_TOTAL];
// CSR scratch
__device__ int g_deg[N_NODES];
__device__ int g_off[N_NODES];
__device__ int g_cursor[N_NODES];
__device__ int g_part[64];
__device__ int g_csr_src[E_EDGES];
__device__ int g_is64;

// weight pack offsets (elements)
#define OFF_S1  0
#define OFF_S2  32768
#define OFF_S3  294912
#define OFF_S4  557056
#define OFF_CAT 819200
#define OFF_M2  950272
#define OFF_L2  966656

__device__ __forceinline__ uint32_t smem_u32(const void* p) {
    uint32_t a;
    asm("{ .reg .u64 t; cvta.to.shared.u64 t, %1; cvt.u32.u64 %0, t; }" : "=r"(a) : "l"(p));
    return a;
}
#define SW128(o) ((o) ^ (((o) >> 3) & 0x70))

// ---------------- edge-index helpers ----------------
__global__ void detect_idx_kernel(const unsigned long long* ei) {
    if (blockIdx.x == 0 && threadIdx.x == 0) {
        int ok = 1;
        #pragma unroll
        for (int i = 0; i < 16; i++)
            if (ei[i] >= (unsigned long long)N_NODES) ok = 0;
        g_is64 = ok;
    }
}
__device__ __forceinline__ void load_edge(const void* ei_raw, int e, int& s, int& d) {
    if (g_is64) {
        const long long* p = (const long long*)ei_raw;
        s = (int)__ldg(p + e); d = (int)__ldg(p + E_EDGES + e);
    } else {
        const int* p = (const int*)ei_raw;
        s = __ldg(p + e); d = __ldg(p + E_EDGES + e);
    }
}

// ---------------- CSR build ----------------
__global__ void zero_deg_kernel(int* deg) {
    int i = blockIdx.x * blockDim.x + threadIdx.x;
    if (i < N_NODES) deg[i] = 0;
}
__global__ void hist_kernel(const void* ei, int* deg) {
    int e = blockIdx.x * blockDim.x + threadIdx.x;
    if (e >= E_EDGES) return;
    int s, d; load_edge(ei, e, s, d);
    atomicAdd(&deg[d], 1);
}
#define SCAN_B 1024
__global__ void scan_block_kernel(const int* deg, int* off, int* part) {
    __shared__ int sh[SCAN_B];
    int tid = threadIdx.x;
    int i = blockIdx.x * SCAN_B + tid;
    int v = (i < N_NODES) ? deg[i] : 0;
    sh[tid] = v;
    __syncthreads();
    for (int ofs = 1; ofs < SCAN_B; ofs <<= 1) {
        int t = (tid >= ofs) ? sh[tid - ofs] : 0;
        __syncthreads();
        sh[tid] += t;
        __syncthreads();
    }
    if (i < N_NODES) off[i] = sh[tid] - v;   // exclusive
    if (tid == SCAN_B - 1) part[blockIdx.x] = sh[tid];
}
__global__ void scan_part_kernel(int* part, int nb) {
    if (threadIdx.x == 0 && blockIdx.x == 0) {
        int run = 0;
        for (int b = 0; b < nb; b++) { int t = part[b]; part[b] = run; run += t; }
    }
}
__global__ void scan_add_kernel(int* off, int* cursor, const int* part) {
    int i = blockIdx.x * SCAN_B + threadIdx.x;
    if (i < N_NODES) {
        int o = off[i] + part[blockIdx.x];
        off[i] = o;
        cursor[i] = o;
    }
}
__global__ void csr_fill_kernel(const void* ei, int* cursor, int* csr_src) {
    int e = blockIdx.x * blockDim.x + threadIdx.x;
    if (e >= E_EDGES) return;
    int s, d; load_edge(ei, e, s, d);
    int pos = atomicAdd(&cursor[d], 1);
    csr_src[pos] = s;
}

// ---------------- fused aggregations ----------------
__device__ __forceinline__ void f4add(float4& a, float4 b) {
    a.x += b.x; a.y += b.y; a.z += b.z; a.w += b.w;
}

// agg64: out = x[n] + sum_{s in N(n)} x[s]  -> bf16 hi/lo splits directly
// one warp per node, lane covers cols 2*lane..2*lane+1
__global__ __launch_bounds__(256) void agg64_split_kernel(
    const float* __restrict__ x, const int* __restrict__ off, const int* __restrict__ deg,
    const int* __restrict__ csr, __nv_bfloat16* __restrict__ ah, __nv_bfloat16* __restrict__ al)
{
    int w = (blockIdx.x * blockDim.x + threadIdx.x) >> 5;
    int lane = threadIdx.x & 31;
    if (w >= N_NODES) return;
    float2 acc = ((const float2*)(x + (size_t)w * 64))[lane];
    int o = off[w], dg = deg[w];
    for (int k = 0; k < dg; k++) {
        int s = __ldg(csr + o + k);
        float2 v = __ldg((const float2*)(x + (size_t)s * 64) + lane);
        acc.x += v.x; acc.y += v.y;
    }
    __nv_bfloat16 h0 = __float2bfloat16(acc.x), h1 = __float2bfloat16(acc.y);
    __nv_bfloat16 l0 = __float2bfloat16(acc.x - __bfloat162float(h0));
    __nv_bfloat16 l1 = __float2bfloat16(acc.y - __bfloat162float(h1));
    ((__nv_bfloat162*)(ah + (size_t)w * 64))[lane] = __nv_bfloat162(h0, h1);
    ((__nv_bfloat162*)(al + (size_t)w * 64))[lane] = __nv_bfloat162(l0, l1);
}

// agg256 + both head prologues:
//   acc = t256[n] + sum t256[s]  (256 cols; lane has float4 at 4*lane and 128+4*lane)
//   head-mu  input = split(relu(acc[0:128]   + b_m1)) -> bh/bl[n*128]
//   head-lv  input = split(relu(acc[128:256] + b_l1)) -> bh/bl[N*128 + n*128]
__global__ __launch_bounds__(256) void agg256_heads_kernel(
    const float* __restrict__ t256, const int* __restrict__ off, const int* __restrict__ deg,
    const int* __restrict__ csr, const float* __restrict__ bm1, const float* __restrict__ bl1,
    __nv_bfloat16* __restrict__ bh, __nv_bfloat16* __restrict__ bl)
{
    int w = (blockIdx.x * blockDim.x + threadIdx.x) >> 5;
    int lane = threadIdx.x & 31;
    if (w >= N_NODES) return;
    const float4* base = (const float4*)(t256 + (size_t)w * 256);
    float4 a = __ldg(base + lane);
    float4 b = __ldg(base + 32 + lane);
    int o = off[w], dg = deg[w];
    for (int k = 0; k < dg; k++) {
        int s = __ldg(csr + o + k);
        const float4* sp = (const float4*)(t256 + (size_t)s * 256);
        f4add(a, __ldg(sp + lane));
        f4add(b, __ldg(sp + 32 + lane));
    }
    // head mu
    {
        float4 bias = __ldg((const float4*)bm1 + lane);
        float v[4] = { fmaxf(a.x + bias.x, 0.f), fmaxf(a.y + bias.y, 0.f),
                       fmaxf(a.z + bias.z, 0.f), fmaxf(a.w + bias.w, 0.f) };
        __nv_bfloat16 h[4], l[4];
        #pragma unroll
        for (int i = 0; i < 4; i++) { h[i] = __float2bfloat16(v[i]); l[i] = __float2bfloat16(v[i] - __bfloat162float(h[i])); }
        size_t base_o = (size_t)w * 128 + lane * 4;
        ((__nv_bfloat162*)(bh + base_o))[0] = __nv_bfloat162(h[0], h[1]);
        ((__nv_bfloat162*)(bh + base_o))[1] = __nv_bfloat162(h[2], h[3]);
        ((__nv_bfloat162*)(bl + base_o))[0] = __nv_bfloat162(l[0], l[1]);
        ((__nv_bfloat162*)(bl + base_o))[1] = __nv_bfloat162(l[2], l[3]);
    }
    // head logvar
    {
        float4 bias = __ldg((const float4*)bl1 + lane);
        float v[4] = { fmaxf(b.x + bias.x, 0.f), fmaxf(b.y + bias.y, 0.f),
                       fmaxf(b.z + bias.z, 0.f), fmaxf(b.w + bias.w, 0.f) };
        __nv_bfloat16 h[4], l[4];
        #pragma unroll
        for (int i = 0; i < 4; i++) { h[i] = __float2bfloat16(v[i]); l[i] = __float2bfloat16(v[i] - __bfloat162float(h[i])); }
        size_t base_o = (size_t)N_NODES * 128 + (size_t)w * 128 + lane * 4;
        ((__nv_bfloat162*)(bh + base_o))[0] = __nv_bfloat162(h[0], h[1]);
        ((__nv_bfloat162*)(bh + base_o))[1] = __nv_bfloat162(h[2], h[3]);
        ((__nv_bfloat162*)(bl + base_o))[0] = __nv_bfloat162(l[0], l[1]);
        ((__nv_bfloat162*)(bl + base_o))[1] = __nv_bfloat162(l[2], l[3]);
    }
}

// ---------------- batched weight split ----------------
struct WSrc { const float2* p[8]; };
// segment starts in float2 units (element offsets / 2)
__constant__ int c_dummy; // keep constant bank untouched otherwise
__global__ void split_weights_kernel(WSrc ws, __nv_bfloat162* __restrict__ hi, __nv_bfloat162* __restrict__ lo) {
    int i = blockIdx.x * blockDim.x + threadIdx.x;
    const int ends[9]   = {16384, 147456, 278528, 409600, 442368, 475136, 483328, 491520, 491520};
    const int starts[9] = {0, 16384, 147456, 278528, 409600, 442368, 475136, 483328, 491520};
    if (i >= 491520) return;
    int seg = 0;
    #pragma unroll
    for (int s = 0; s < 8; s++) if (i >= ends[s]) seg = s + 1;
    const float2* src = (seg < 8) ? ws.p[seg] : ws.p[7];
    // seg 4 is W_l1 (second half of CAT) — ws.p holds it at slot 4; mapping below
    float2 v = src[i - starts[seg]];
    __nv_bfloat16 h0 = __float2bfloat16(v.x), h1 = __float2bfloat16(v.y);
    __nv_bfloat16 l0 = __float2bfloat16(v.x - __bfloat162float(h0));
    __nv_bfloat16 l1 = __float2bfloat16(v.y - __bfloat162float(h1));
    hi[i] = __nv_bfloat162(h0, h1);
    lo[i] = __nv_bfloat162(l0, l1);
}

// ---------------- mma.sync split-bf16 GEMM (unchanged engine from R4) ----------------
#define GT 256
#define SMEM_GEMM 131072

#define LDSM4(r0, r1, r2, r3, a) \
    asm volatile("ldmatrix.sync.aligned.m8n8.x4.shared.b16 {%0,%1,%2,%3}, [%4];" \
                 : "=r"(r0), "=r"(r1), "=r"(r2), "=r"(r3) : "r"(a))

#define HMMA(c, a0, a1, a2, a3, b0, b1) \
    asm volatile("mma.sync.aligned.m16n8k16.row.col.f32.bf16.bf16.f32 " \
                 "{%0,%1,%2,%3}, {%4,%5,%6,%7}, {%8,%9}, {%0,%1,%2,%3};" \
                 : "+f"((c)[0]), "+f"((c)[1]), "+f"((c)[2]), "+f"((c)[3]) \
                 : "r"(a0), "r"(a1), "r"(a2), "r"(a3), "r"(b0), "r"(b1))

__device__ __forceinline__ void cp16(uint32_t saddr, const void* gptr, uint32_t sz) {
    asm volatile("cp.async.cg.shared.global [%0], [%1], 16, %2;"
                 :: "r"(saddr), "l"(gptr), "r"(sz) : "memory");
}
#define CP_COMMIT() asm volatile("cp.async.commit_group;" ::: "memory")
#define CP_WAIT(n)  asm volatile("cp.async.wait_group %0;" :: "n"(n) : "memory")

template <int ACT, bool EMITF, bool EMITB, bool HASB>
__global__ __launch_bounds__(GT, 1)
void gemm_tc(const __nv_bfloat16* __restrict__ Ah, const __nv_bfloat16* __restrict__ Al, int lda,
             const __nv_bfloat16* __restrict__ Wh, const __nv_bfloat16* __restrict__ Wl,
             const float* __restrict__ bias,
             float* __restrict__ C, int ldc,
             __nv_bfloat16* __restrict__ Ch, __nv_bfloat16* __restrict__ Cl, int ldcb,
             int M, int K)
{
    extern __shared__ char smem[];
    const uint32_t sb = smem_u32(smem);

    const int tid = threadIdx.x;
    const int wid = tid >> 5;
    const int lane = tid & 31;
    const int m0 = blockIdx.y * 128;
    const int n0 = blockIdx.x * 128;
    const int wm = (wid & 1) * 64;
    const int wn = (wid >> 1) * 32;

    float acc[4][4][4] = {};

    const int srow = tid >> 3, sg = tid & 7;

    auto stage = [&](int buf, int k0) {
        const uint32_t tb = sb + buf * 65536;
        #pragma unroll
        for (int t = 0; t < 4; t++) {
            const int row = srow + t * 32;
            const uint32_t so = SW128((uint32_t)(row * 128 + sg * 16));
            const int ar = m0 + row;
            const int ok = (ar < M);
            const size_t ao = (size_t)(ok ? ar : 0) * lda + k0 + sg * 8;
            cp16(tb + 0     + so, Ah + ao, ok ? 16 : 0);
            cp16(tb + 16384 + so, Al + ao, ok ? 16 : 0);
            const size_t wo = (size_t)(n0 + row) * K + k0 + sg * 8;
            cp16(tb + 32768 + so, Wh + wo, 16);
            cp16(tb + 49152 + so, Wl + wo, 16);
        }
        CP_COMMIT();
    };

    const int o = lane >> 3, r = lane & 7;
    int aRow[4];
    #pragma unroll
    for (int i = 0; i < 4; i++) aRow[i] = (wm + 16 * i + (o & 1) * 8 + r) * 128 + (o >> 1) * 16;
    int bRow[2];
    #pragma unroll
    for (int p = 0; p < 2; p++) bRow[p] = (wn + p * 16 + (o >> 1) * 8 + r) * 128 + (o & 1) * 16;

    const int nchunks = K >> 6;
    stage(0, 0);
    for (int c = 0; c < nchunks; c++) {
        if (c + 1 < nchunks) stage((c + 1) & 1, (c + 1) << 6);
        if (c + 1 < nchunks) { CP_WAIT(1); } else { CP_WAIT(0); }
        __syncthreads();

        const uint32_t tb = sb + (c & 1) * 65536;
        #pragma unroll
        for (int ks = 0; ks < 4; ks++) {
            const int kb = ks * 32;
            uint32_t ah[4][4], al[4][4], wh[2][4], wl[2][4];
            #pragma unroll
            for (int i = 0; i < 4; i++) {
                const uint32_t ad = SW128((uint32_t)(aRow[i] + kb));
                LDSM4(ah[i][0], ah[i][1], ah[i][2], ah[i][3], tb + ad);
                LDSM4(al[i][0], al[i][1], al[i][2], al[i][3], tb + 16384 + ad);
            }
            #pragma unroll
            for (int p = 0; p < 2; p++) {
                const uint32_t bd = SW128((uint32_t)(bRow[p] + kb));
                LDSM4(wh[p][0], wh[p][1], wh[p][2], wh[p][3], tb + 32768 + bd);
                LDSM4(wl[p][0], wl[p][1], wl[p][2], wl[p][3], tb + 49152 + bd);
            }
            #pragma unroll
            for (int i = 0; i < 4; i++) {
                #pragma unroll
                for (int j = 0; j < 4; j++) {
                    const uint32_t bh0 = wh[j >> 1][(j & 1) * 2], bh1 = wh[j >> 1][(j & 1) * 2 + 1];
                    const uint32_t bl0 = wl[j >> 1][(j & 1) * 2], bl1 = wl[j >> 1][(j & 1) * 2 + 1];
                    HMMA(acc[i][j], ah[i][0], ah[i][1], ah[i][2], ah[i][3], bh0, bh1);
                    HMMA(acc[i][j], ah[i][0], ah[i][1], ah[i][2], ah[i][3], bl0, bl1);
                    HMMA(acc[i][j], al[i][0], al[i][1], al[i][2], al[i][3], bh0, bh1);
                }
            }
        }
        __syncthreads();
    }

    const int gid = lane >> 2, tig = lane & 3;
    #pragma unroll
    for (int i = 0; i < 4; i++) {
        #pragma unroll
        for (int h = 0; h < 2; h++) {
            const int row = m0 + wm + 16 * i + 8 * h + gid;
            if (row >= M) continue;
            #pragma unroll
            for (int j = 0; j < 4; j++) {
                const int col = n0 + wn + 8 * j + 2 * tig;
                float v0 = acc[i][j][2 * h], v1 = acc[i][j][2 * h + 1];
                if (HASB) { v0 += __ldg(bias + col); v1 += __ldg(bias + col + 1); }
                if (ACT == 1) { v0 = (v0 > 0.f) ? v0 : 0.1f * v0; v1 = (v1 > 0.f) ? v1 : 0.1f * v1; }
                if (ACT == 2) { v0 = fmaxf(v0, 0.f); v1 = fmaxf(v1, 0.f); }
                if (EMITF) {
                    *(float2*)&C[(size_t)row * ldc + col] = make_float2(v0, v1);
                }
                if (EMITB) {
                    __nv_bfloat16 h0 = __float2bfloat16(v0), h1 = __float2bfloat16(v1);
                    __nv_bfloat16 l0 = __float2bfloat16(v0 - __bfloat162float(h0));
                    __nv_bfloat16 l1 = __float2bfloat16(v1 - __bfloat162float(h1));
                    *(__nv_bfloat162*)&Ch[(size_t)row * ldcb + col] = __nv_bfloat162(h0, h1);
                    *(__nv_bfloat162*)&Cl[(size_t)row * ldcb + col] = __nv_bfloat162(l0, l1);
                }
            }
        }
    }
}

// ---------------- launch ----------------
extern "C" void kernel_launch(void* const* d_in, const int* in_sizes, int n_in,
                              void* d_out, int out_size) {
    const float* x    = (const float*)d_in[0];
    const void*  ei   = d_in[1];
    const float* W_s1 = (const float*)d_in[2];
    const float* b_s1 = (const float*)d_in[3];
    const float* W_s2 = (const float*)d_in[4];
    const float* b_s2 = (const float*)d_in[5];
    const float* W_s3 = (const float*)d_in[6];
    const float* b_s3 = (const float*)d_in[7];
    const float* W_s4 = (const float*)d_in[8];
    const float* b_s4 = (const float*)d_in[9];
    const float* W_m1 = (const float*)d_in[10];
    const float* b_m1 = (const float*)d_in[11];
    const float* W_m2 = (const float*)d_in[12];
    const float* b_m2 = (const float*)d_in[13];
    const float* W_l1 = (const float*)d_in[14];
    const float* b_l1 = (const float*)d_in[15];
    const float* W_l2 = (const float*)d_in[16];
    const float* b_l2 = (const float*)d_in[17];
    float* out = (float*)d_out;

    float *t256;
    __nv_bfloat16 *ah, *al, *bh, *bl, *wh, *wl;
    int *deg, *off, *cursor, *part, *csr;
    cudaGetSymbolAddress((void**)&t256, g_t256);
    cudaGetSymbolAddress((void**)&ah, g_ah);
    cudaGetSymbolAddress((void**)&al, g_al);
    cudaGetSymbolAddress((void**)&bh, g_bh);
    cudaGetSymbolAddress((void**)&bl, g_bl);
    cudaGetSymbolAddress((void**)&wh, g_wh);
    cudaGetSymbolAddress((void**)&wl, g_wl);
    cudaGetSymbolAddress((void**)&deg, g_deg);
    cudaGetSymbolAddress((void**)&off, g_off);
    cudaGetSymbolAddress((void**)&cursor, g_cursor);
    cudaGetSymbolAddress((void**)&part, g_part);
    cudaGetSymbolAddress((void**)&csr, g_csr_src);

    static bool attr_done = false;
    if (!attr_done) {
        cudaFuncSetAttribute(gemm_tc<1, false, true,  true >, cudaFuncAttributeMaxDynamicSharedMemorySize, SMEM_GEMM);
        cudaFuncSetAttribute(gemm_tc<2, false, true,  true >, cudaFuncAttributeMaxDynamicSharedMemorySize, SMEM_GEMM);
        cudaFuncSetAttribute(gemm_tc<0, true,  false, false>, cudaFuncAttributeMaxDynamicSharedMemorySize, SMEM_GEMM);
        cudaFuncSetAttribute(gemm_tc<0, true,  false, true >, cudaFuncAttributeMaxDynamicSharedMemorySize, SMEM_GEMM);
        attr_done = true;
    }

    const int M = N_NODES;
    const dim3 blk(GT);
    const dim3 g512(4, (M + 127) / 128);
    const dim3 g256(2, (M + 127) / 128);
    const dim3 g128(1, (M + 127) / 128);
    const int SCAN_NB = (N_NODES + SCAN_B - 1) / SCAN_B;   // 49

    detect_idx_kernel<<<1, 32>>>((const unsigned long long*)ei);

    // ---- weight splits (batched: one kernel for all 8 matrices) ----
    {
        WSrc ws;
        ws.p[0] = (const float2*)W_s1;
        ws.p[1] = (const float2*)W_s2;
        ws.p[2] = (const float2*)W_s3;
        ws.p[3] = (const float2*)W_s4;
        ws.p[4] = (const float2*)W_m1;
        ws.p[5] = (const float2*)W_l1;
        ws.p[6] = (const float2*)W_m2;
        ws.p[7] = (const float2*)W_l2;
        split_weights_kernel<<<(491520 + 255) / 256, 256>>>(ws, (__nv_bfloat162*)wh, (__nv_bfloat162*)wl);
    }

    // ---- CSR build ----
    zero_deg_kernel<<<(N_NODES + 255) / 256, 256>>>(deg);
    hist_kernel<<<(E_EDGES + 255) / 256, 256>>>(ei, deg);
    scan_block_kernel<<<SCAN_NB, SCAN_B>>>(deg, off, part);
    scan_part_kernel<<<1, 32>>>(part, SCAN_NB);
    scan_add_kernel<<<SCAN_NB, SCAN_B>>>(off, cursor, part);
    csr_fill_kernel<<<(E_EDGES + 255) / 256, 256>>>(ei, cursor, csr);

    // ---- agg0 = (I+A)x, fused bf16 split ----
    agg64_split_kernel<<<(N_NODES * 32 + 255) / 256, 256>>>(x, off, deg, csr, ah, al);

    // ---- shared MLP, bf16-split outputs chained through epilogues ----
    gemm_tc<1, false, true, true><<<g512, blk, SMEM_GEMM>>>(ah, al, 64,  wh + OFF_S1, wl + OFF_S1, b_s1, nullptr, 0, bh, bl, 512, M, 64);
    gemm_tc<1, false, true, true><<<g512, blk, SMEM_GEMM>>>(bh, bl, 512, wh + OFF_S2, wl + OFF_S2, b_s2, nullptr, 0, ah, al, 512, M, 512);
    gemm_tc<1, false, true, true><<<g512, blk, SMEM_GEMM>>>(ah, al, 512, wh + OFF_S3, wl + OFF_S3, b_s3, nullptr, 0, bh, bl, 512, M, 512);
    gemm_tc<2, false, true, true><<<g512, blk, SMEM_GEMM>>>(bh, bl, 512, wh + OFF_S4, wl + OFF_S4, b_s4, nullptr, 0, ah, al, 512, M, 512);

    // ---- t256 = h @ [W_m1; W_l1]^T (aggregation commutes with the linear map) ----
    gemm_tc<0, true, false, false><<<g256, blk, SMEM_GEMM>>>(ah, al, 512, wh + OFF_CAT, wl + OFF_CAT, nullptr, t256, 256, nullptr, nullptr, 0, M, 512);

    // ---- agg(256) + both head prologues fused, emits head inputs bh/bl ----
    agg256_heads_kernel<<<(N_NODES * 32 + 255) / 256, 256>>>(t256, off, deg, csr, b_m1, b_l1, bh, bl);

    // ---- heads ----
    gemm_tc<0, true, false, true><<<g128, blk, SMEM_GEMM>>>(bh, bl, 128, wh + OFF_M2, wl + OFF_M2, b_m2, out, 128, nullptr, nullptr, 0, M, 128);
    gemm_tc<0, true, false, true><<<g128, blk, SMEM_GEMM>>>(bh + (size_t)N_NODES * 128, bl + (size_t)N_NODES * 128, 128, wh + OFF_L2, wl + OFF_L2, b_l2, out + (size_t)N_NODES * 128, 128, nullptr, nullptr, 0, M, 128);

    (void)in_sizes; (void)n_in; (void)out_size;
}

// round 7
// speedup vs baseline: 5.9715x; 1.4727x over previous
#include <cuda_runtime.h>
#include <cuda_fp16.h>
#include <cstdint>

#define N_NODES 50000
#define E_EDGES 800000

// ---------------- static scratch (no allocs allowed) ----------------
__device__ float g_t256[N_NODES * 256];
__device__ __half g_ha[N_NODES * 512];
__device__ __half g_hb[N_NODES * 512];
#define W_TOTAL 983040
__device__ __half g_wh[W_TOTAL];
__device__ __half g_wl[W_TOTAL];
// CSR scratch
__device__ int g_deg[N_NODES];
__device__ int g_off[N_NODES];
__device__ int g_cursor[N_NODES];
__device__ int g_part[64];
__device__ int g_csr_src[E_EDGES];
__device__ int g_is64;

// weight pack offsets (elements)
#define OFF_S1  0
#define OFF_S2  32768
#define OFF_S3  294912
#define OFF_S4  557056
#define OFF_CAT 819200
#define OFF_M2  950272
#define OFF_L2  966656

__device__ __forceinline__ uint32_t smem_u32(const void* p) {
    uint32_t a;
    asm("{ .reg .u64 t; cvta.to.shared.u64 t, %1; cvt.u32.u64 %0, t; }" : "=r"(a) : "l"(p));
    return a;
}
#define SW128(o) ((o) ^ (((o) >> 3) & 0x70))

// ---------------- edge-index helpers ----------------
__global__ void detect_idx_kernel(const unsigned long long* ei) {
    if (blockIdx.x == 0 && threadIdx.x == 0) {
        int ok = 1;
        #pragma unroll
        for (int i = 0; i < 16; i++)
            if (ei[i] >= (unsigned long long)N_NODES) ok = 0;
        g_is64 = ok;
    }
}
__device__ __forceinline__ void load_edge(const void* ei_raw, int e, int& s, int& d) {
    if (g_is64) {
        const long long* p = (const long long*)ei_raw;
        s = (int)__ldg(p + e); d = (int)__ldg(p + E_EDGES + e);
    } else {
        const int* p = (const int*)ei_raw;
        s = __ldg(p + e); d = __ldg(p + E_EDGES + e);
    }
}

// ---------------- CSR build ----------------
__global__ void zero_deg_kernel(int* deg) {
    int i = blockIdx.x * blockDim.x + threadIdx.x;
    if (i < N_NODES) deg[i] = 0;
}
__global__ void hist_kernel(const void* ei, int* deg) {
    int e = blockIdx.x * blockDim.x + threadIdx.x;
    if (e >= E_EDGES) return;
    int s, d; load_edge(ei, e, s, d);
    atomicAdd(&deg[d], 1);
}
#define SCAN_B 1024
__global__ void scan_block_kernel(const int* deg, int* off, int* part) {
    __shared__ int sh[SCAN_B];
    int tid = threadIdx.x;
    int i = blockIdx.x * SCAN_B + tid;
    int v = (i < N_NODES) ? deg[i] : 0;
    sh[tid] = v;
    __syncthreads();
    for (int ofs = 1; ofs < SCAN_B; ofs <<= 1) {
        int t = (tid >= ofs) ? sh[tid - ofs] : 0;
        __syncthreads();
        sh[tid] += t;
        __syncthreads();
    }
    if (i < N_NODES) off[i] = sh[tid] - v;   // exclusive
    if (tid == SCAN_B - 1) part[blockIdx.x] = sh[tid];
}
__global__ void scan_part_kernel(int* part, int nb) {
    if (threadIdx.x == 0 && blockIdx.x == 0) {
        int run = 0;
        for (int b = 0; b < nb; b++) { int t = part[b]; part[b] = run; run += t; }
    }
}
__global__ void scan_add_kernel(int* off, int* cursor, const int* part) {
    int i = blockIdx.x * SCAN_B + threadIdx.x;
    if (i < N_NODES) {
        int o = off[i] + part[blockIdx.x];
        off[i] = o;
        cursor[i] = o;
    }
}
__global__ void csr_fill_kernel(const void* ei, int* cursor, int* csr_src) {
    int e = blockIdx.x * blockDim.x + threadIdx.x;
    if (e >= E_EDGES) return;
    int s, d; load_edge(ei, e, s, d);
    int pos = atomicAdd(&cursor[d], 1);
    csr_src[pos] = s;
}

// ---------------- fused aggregations ----------------
__device__ __forceinline__ void f4add(float4& a, float4 b) {
    a.x += b.x; a.y += b.y; a.z += b.z; a.w += b.w;
}

// agg64: out = fp16(x[n] + sum_{s in N(n)} x[s]) ; one warp per node, 2 cols/lane
__global__ __launch_bounds__(256) void agg64_kernel(
    const float* __restrict__ x, const int* __restrict__ off, const int* __restrict__ deg,
    const int* __restrict__ csr, __half* __restrict__ ha)
{
    int w = (blockIdx.x * blockDim.x + threadIdx.x) >> 5;
    int lane = threadIdx.x & 31;
    if (w >= N_NODES) return;
    float2 acc0 = ((const float2*)(x + (size_t)w * 64))[lane];
    float2 acc1 = make_float2(0.f, 0.f);
    int o = off[w], dg = deg[w];
    int k = 0;
    for (; k + 2 <= dg; k += 2) {
        int s0 = __ldg(csr + o + k);
        int s1 = __ldg(csr + o + k + 1);
        float2 v0 = __ldg((const float2*)(x + (size_t)s0 * 64) + lane);
        float2 v1 = __ldg((const float2*)(x + (size_t)s1 * 64) + lane);
        acc0.x += v0.x; acc0.y += v0.y;
        acc1.x += v1.x; acc1.y += v1.y;
    }
    if (k < dg) {
        int s0 = __ldg(csr + o + k);
        float2 v0 = __ldg((const float2*)(x + (size_t)s0 * 64) + lane);
        acc0.x += v0.x; acc0.y += v0.y;
    }
    acc0.x += acc1.x; acc0.y += acc1.y;
    ((__half2*)(ha + (size_t)w * 64))[lane] = __floats2half2_rn(acc0.x, acc0.y);
}

// agg256 + both head prologues (fp16 outputs):
//   acc = t256[n] + sum t256[s]
//   mu  input = fp16(relu(acc[0:128]   + b_m1)) -> hh[n*128]
//   lv  input = fp16(relu(acc[128:256] + b_l1)) -> hh[N*128 + n*128]
__global__ __launch_bounds__(256) void agg256_heads_kernel(
    const float* __restrict__ t256, const int* __restrict__ off, const int* __restrict__ deg,
    const int* __restrict__ csr, const float* __restrict__ bm1, const float* __restrict__ bl1,
    __half* __restrict__ hh)
{
    int w = (blockIdx.x * blockDim.x + threadIdx.x) >> 5;
    int lane = threadIdx.x & 31;
    if (w >= N_NODES) return;
    const float4* base = (const float4*)(t256 + (size_t)w * 256);
    float4 a0 = __ldg(base + lane);
    float4 b0 = __ldg(base + 32 + lane);
    float4 a1 = make_float4(0.f, 0.f, 0.f, 0.f);
    float4 b1 = make_float4(0.f, 0.f, 0.f, 0.f);
    int o = off[w], dg = deg[w];
    int k = 0;
    for (; k + 2 <= dg; k += 2) {
        int s0 = __ldg(csr + o + k);
        int s1 = __ldg(csr + o + k + 1);
        const float4* p0 = (const float4*)(t256 + (size_t)s0 * 256);
        const float4* p1 = (const float4*)(t256 + (size_t)s1 * 256);
        f4add(a0, __ldg(p0 + lane));
        f4add(a1, __ldg(p1 + lane));
        f4add(b0, __ldg(p0 + 32 + lane));
        f4add(b1, __ldg(p1 + 32 + lane));
    }
    if (k < dg) {
        int s0 = __ldg(csr + o + k);
        const float4* p0 = (const float4*)(t256 + (size_t)s0 * 256);
        f4add(a0, __ldg(p0 + lane));
        f4add(b0, __ldg(p0 + 32 + lane));
    }
    f4add(a0, a1); f4add(b0, b1);
    {
        float4 bias = __ldg((const float4*)bm1 + lane);
        __half2* ph = (__half2*)(hh + (size_t)w * 128 + lane * 4);
        ph[0] = __floats2half2_rn(fmaxf(a0.x + bias.x, 0.f), fmaxf(a0.y + bias.y, 0.f));
        ph[1] = __floats2half2_rn(fmaxf(a0.z + bias.z, 0.f), fmaxf(a0.w + bias.w, 0.f));
    }
    {
        float4 bias = __ldg((const float4*)bl1 + lane);
        __half2* ph = (__half2*)(hh + (size_t)N_NODES * 128 + (size_t)w * 128 + lane * 4);
        ph[0] = __floats2half2_rn(fmaxf(b0.x + bias.x, 0.f), fmaxf(b0.y + bias.y, 0.f));
        ph[1] = __floats2half2_rn(fmaxf(b0.z + bias.z, 0.f), fmaxf(b0.w + bias.w, 0.f));
    }
}

// ---------------- batched weight split: fp32 -> fp16 hi + fp16 lo ----------------
struct WSrc { const float2* p[8]; };
__global__ void split_weights_kernel(WSrc ws, __half2* __restrict__ hi, __half2* __restrict__ lo) {
    int i = blockIdx.x * blockDim.x + threadIdx.x;
    const int ends[8]   = {16384, 147456, 278528, 409600, 442368, 475136, 483328, 491520};
    const int starts[8] = {0, 16384, 147456, 278528, 409600, 442368, 475136, 483328};
    if (i >= 491520) return;
    int seg = 0;
    #pragma unroll
    for (int s = 0; s < 7; s++) if (i >= ends[s]) seg = s + 1;
    float2 v = ws.p[seg][i - starts[seg]];
    __half h0 = __float2half(v.x), h1 = __float2half(v.y);
    __half l0 = __float2half(v.x - __half2float(h0));
    __half l1 = __float2half(v.y - __half2float(h1));
    hi[i] = __halves2half2(h0, h1);
    lo[i] = __halves2half2(l0, l1);
}

// ---------------- mma.sync fp16 2-product GEMM ----------------
// C[M,Nn] = act(A[M,K] @ W[Nn,K]^T + bias); A fp16, W = Wh + Wl fp16 split.
// acc += A*Wh + A*Wl (fp32 accum). CTA tile 128x128, 8 warps of 64x32,
// K in 64-elem SW128 chunks, cp.async double buffer (2 x 48KB smem -> 2 CTA/SM).
#define GT 256
#define SMEM_GEMM 98304
#define BUFB 49152

#define LDSM4(r0, r1, r2, r3, a) \
    asm volatile("ldmatrix.sync.aligned.m8n8.x4.shared.b16 {%0,%1,%2,%3}, [%4];" \
                 : "=r"(r0), "=r"(r1), "=r"(r2), "=r"(r3) : "r"(a))

#define HMMA(c, a0, a1, a2, a3, b0, b1) \
    asm volatile("mma.sync.aligned.m16n8k16.row.col.f32.f16.f16.f32 " \
                 "{%0,%1,%2,%3}, {%4,%5,%6,%7}, {%8,%9}, {%0,%1,%2,%3};" \
                 : "+f"((c)[0]), "+f"((c)[1]), "+f"((c)[2]), "+f"((c)[3]) \
                 : "r"(a0), "r"(a1), "r"(a2), "r"(a3), "r"(b0), "r"(b1))

__device__ __forceinline__ void cp16(uint32_t saddr, const void* gptr, uint32_t sz) {
    asm volatile("cp.async.cg.shared.global [%0], [%1], 16, %2;"
                 :: "r"(saddr), "l"(gptr), "r"(sz) : "memory");
}
#define CP_COMMIT() asm volatile("cp.async.commit_group;" ::: "memory")
#define CP_WAIT(n)  asm volatile("cp.async.wait_group %0;" :: "n"(n) : "memory")

template <int ACT, bool EMITF, bool EMITH, bool HASB>
__global__ __launch_bounds__(GT, 2)
void gemm_tc(const __half* __restrict__ A, int lda,
             const __half* __restrict__ Wh, const __half* __restrict__ Wl,
             const float* __restrict__ bias,
             float* __restrict__ C, int ldc,
             __half* __restrict__ Ch, int ldch,
             int M, int K)
{
    extern __shared__ char smem[];
    const uint32_t sb = smem_u32(smem);

    const int tid = threadIdx.x;
    const int wid = tid >> 5;
    const int lane = tid & 31;
    const int m0 = blockIdx.y * 128;
    const int n0 = blockIdx.x * 128;
    const int wm = (wid & 1) * 64;
    const int wn = (wid >> 1) * 32;

    float acc[4][4][4] = {};

    const int srow = tid >> 3, sg = tid & 7;

    auto stage = [&](int buf, int k0) {
        const uint32_t tb = sb + buf * BUFB;
        #pragma unroll
        for (int t = 0; t < 4; t++) {
            const int row = srow + t * 32;
            const uint32_t so = SW128((uint32_t)(row * 128 + sg * 16));
            const int ar = m0 + row;
            const int ok = (ar < M);
            const size_t ao = (size_t)(ok ? ar : 0) * lda + k0 + sg * 8;
            cp16(tb + 0     + so, A + ao, ok ? 16 : 0);
            const size_t wo = (size_t)(n0 + row) * K + k0 + sg * 8;
            cp16(tb + 16384 + so, Wh + wo, 16);
            cp16(tb + 32768 + so, Wl + wo, 16);
        }
        CP_COMMIT();
    };

    const int o = lane >> 3, r = lane & 7;
    int aRow[4];
    #pragma unroll
    for (int i = 0; i < 4; i++) aRow[i] = (wm + 16 * i + (o & 1) * 8 + r) * 128 + (o >> 1) * 16;
    int bRow[2];
    #pragma unroll
    for (int p = 0; p < 2; p++) bRow[p] = (wn + p * 16 + (o >> 1) * 8 + r) * 128 + (o & 1) * 16;

    const int nchunks = K >> 6;
    stage(0, 0);
    for (int c = 0; c < nchunks; c++) {
        if (c + 1 < nchunks) stage((c + 1) & 1, (c + 1) << 6);
        if (c + 1 < nchunks) { CP_WAIT(1); } else { CP_WAIT(0); }
        __syncthreads();

        const uint32_t tb = sb + (c & 1) * BUFB;
        #pragma unroll
        for (int ks = 0; ks < 4; ks++) {
            const int kb = ks * 32;
            uint32_t af[4][4], wh[2][4], wl[2][4];
            #pragma unroll
            for (int i = 0; i < 4; i++) {
                const uint32_t ad = SW128((uint32_t)(aRow[i] + kb));
                LDSM4(af[i][0], af[i][1], af[i][2], af[i][3], tb + ad);
            }
            #pragma unroll
            for (int p = 0; p < 2; p++) {
                const uint32_t bd = SW128((uint32_t)(bRow[p] + kb));
                LDSM4(wh[p][0], wh[p][1], wh[p][2], wh[p][3], tb + 16384 + bd);
                LDSM4(wl[p][0], wl[p][1], wl[p][2], wl[p][3], tb + 32768 + bd);
            }
            #pragma unroll
            for (int i = 0; i < 4; i++) {
                #pragma unroll
                for (int j = 0; j < 4; j++) {
                    const uint32_t bh0 = wh[j >> 1][(j & 1) * 2], bh1 = wh[j >> 1][(j & 1) * 2 + 1];
                    const uint32_t bl0 = wl[j >> 1][(j & 1) * 2], bl1 = wl[j >> 1][(j & 1) * 2 + 1];
                    HMMA(acc[i][j], af[i][0], af[i][1], af[i][2], af[i][3], bh0, bh1);
                    HMMA(acc[i][j], af[i][0], af[i][1], af[i][2], af[i][3], bl0, bl1);
                }
            }
        }
        __syncthreads();
    }

    const int gid = lane >> 2, tig = lane & 3;
    #pragma unroll
    for (int i = 0; i < 4; i++) {
        #pragma unroll
        for (int h = 0; h < 2; h++) {
            const int row = m0 + wm + 16 * i + 8 * h + gid;
            if (row >= M) continue;
            #pragma unroll
            for (int j = 0; j < 4; j++) {
                const int col = n0 + wn + 8 * j + 2 * tig;
                float v0 = acc[i][j][2 * h], v1 = acc[i][j][2 * h + 1];
                if (HASB) { v0 += __ldg(bias + col); v1 += __ldg(bias + col + 1); }
                if (ACT == 1) { v0 = (v0 > 0.f) ? v0 : 0.1f * v0; v1 = (v1 > 0.f) ? v1 : 0.1f * v1; }
                if (ACT == 2) { v0 = fmaxf(v0, 0.f); v1 = fmaxf(v1, 0.f); }
                if (EMITF) {
                    *(float2*)&C[(size_t)row * ldc + col] = make_float2(v0, v1);
                }
                if (EMITH) {
                    *(__half2*)&Ch[(size_t)row * ldch + col] = __floats2half2_rn(v0, v1);
                }
            }
        }
    }
}

// ---------------- launch ----------------
extern "C" void kernel_launch(void* const* d_in, const int* in_sizes, int n_in,
                              void* d_out, int out_size) {
    const float* x    = (const float*)d_in[0];
    const void*  ei   = d_in[1];
    const float* W_s1 = (const float*)d_in[2];
    const float* b_s1 = (const float*)d_in[3];
    const float* W_s2 = (const float*)d_in[4];
    const float* b_s2 = (const float*)d_in[5];
    const float* W_s3 = (const float*)d_in[6];
    const float* b_s3 = (const float*)d_in[7];
    const float* W_s4 = (const float*)d_in[8];
    const float* b_s4 = (const float*)d_in[9];
    const float* W_m1 = (const float*)d_in[10];
    const float* b_m1 = (const float*)d_in[11];
    const float* W_m2 = (const float*)d_in[12];
    const float* b_m2 = (const float*)d_in[13];
    const float* W_l1 = (const float*)d_in[14];
    const float* b_l1 = (const float*)d_in[15];
    const float* W_l2 = (const float*)d_in[16];
    const float* b_l2 = (const float*)d_in[17];
    float* out = (float*)d_out;

    float* t256;
    __half *ha, *hb, *wh, *wl;
    int *deg, *off, *cursor, *part, *csr;
    cudaGetSymbolAddress((void**)&t256, g_t256);
    cudaGetSymbolAddress((void**)&ha, g_ha);
    cudaGetSymbolAddress((void**)&hb, g_hb);
    cudaGetSymbolAddress((void**)&wh, g_wh);
    cudaGetSymbolAddress((void**)&wl, g_wl);
    cudaGetSymbolAddress((void**)&deg, g_deg);
    cudaGetSymbolAddress((void**)&off, g_off);
    cudaGetSymbolAddress((void**)&cursor, g_cursor);
    cudaGetSymbolAddress((void**)&part, g_part);
    cudaGetSymbolAddress((void**)&csr, g_csr_src);

    static bool attr_done = false;
    if (!attr_done) {
        cudaFuncSetAttribute(gemm_tc<1, false, true,  true >, cudaFuncAttributeMaxDynamicSharedMemorySize, SMEM_GEMM);
        cudaFuncSetAttribute(gemm_tc<2, false, true,  true >, cudaFuncAttributeMaxDynamicSharedMemorySize, SMEM_GEMM);
        cudaFuncSetAttribute(gemm_tc<0, true,  false, false>, cudaFuncAttributeMaxDynamicSharedMemorySize, SMEM_GEMM);
        cudaFuncSetAttribute(gemm_tc<0, true,  false, true >, cudaFuncAttributeMaxDynamicSharedMemorySize, SMEM_GEMM);
        attr_done = true;
    }

    const int M = N_NODES;
    const dim3 blk(GT);
    const dim3 g512(4, (M + 127) / 128);
    const dim3 g256(2, (M + 127) / 128);
    const dim3 g128(1, (M + 127) / 128);
    const int SCAN_NB = (N_NODES + SCAN_B - 1) / SCAN_B;

    detect_idx_kernel<<<1, 32>>>((const unsigned long long*)ei);

    // ---- weight splits (one kernel for all 8 matrices) ----
    {
        WSrc ws;
        ws.p[0] = (const float2*)W_s1;
        ws.p[1] = (const float2*)W_s2;
        ws.p[2] = (const float2*)W_s3;
        ws.p[3] = (const float2*)W_s4;
        ws.p[4] = (const float2*)W_m1;
        ws.p[5] = (const float2*)W_l1;
        ws.p[6] = (const float2*)W_m2;
        ws.p[7] = (const float2*)W_l2;
        split_weights_kernel<<<(491520 + 255) / 256, 256>>>(ws, (__half2*)wh, (__half2*)wl);
    }

    // ---- CSR build ----
    zero_deg_kernel<<<(N_NODES + 255) / 256, 256>>>(deg);
    hist_kernel<<<(E_EDGES + 255) / 256, 256>>>(ei, deg);
    scan_block_kernel<<<SCAN_NB, SCAN_B>>>(deg, off, part);
    scan_part_kernel<<<1, 32>>>(part, SCAN_NB);
    scan_add_kernel<<<SCAN_NB, SCAN_B>>>(off, cursor, part);
    csr_fill_kernel<<<(E_EDGES + 255) / 256, 256>>>(ei, cursor, csr);

    // ---- agg0 = (I+A)x -> fp16 ----
    agg64_kernel<<<(N_NODES * 32 + 255) / 256, 256>>>(x, off, deg, csr, ha);

    // ---- shared MLP, fp16 activations chained through epilogues ----
    gemm_tc<1, false, true, true><<<g512, blk, SMEM_GEMM>>>(ha, 64,  wh + OFF_S1, wl + OFF_S1, b_s1, nullptr, 0, hb, 512, M, 64);
    gemm_tc<1, false, true, true><<<g512, blk, SMEM_GEMM>>>(hb, 512, wh + OFF_S2, wl + OFF_S2, b_s2, nullptr, 0, ha, 512, M, 512);
    gemm_tc<1, false, true, true><<<g512, blk, SMEM_GEMM>>>(ha, 512, wh + OFF_S3, wl + OFF_S3, b_s3, nullptr, 0, hb, 512, M, 512);
    gemm_tc<2, false, true, true><<<g512, blk, SMEM_GEMM>>>(hb, 512, wh + OFF_S4, wl + OFF_S4, b_s4, nullptr, 0, ha, 512, M, 512);

    // ---- t256 = h @ [W_m1; W_l1]^T (aggregation commutes with the linear map) ----
    gemm_tc<0, true, false, false><<<g256, blk, SMEM_GEMM>>>(ha, 512, wh + OFF_CAT, wl + OFF_CAT, nullptr, t256, 256, nullptr, 0, M, 512);

    // ---- agg(256) + both head prologues fused, emits fp16 head inputs into hb ----
    agg256_heads_kernel<<<(N_NODES * 32 + 255) / 256, 256>>>(t256, off, deg, csr, b_m1, b_l1, hb);

    // ---- heads ----
    gemm_tc<0, true, false, true><<<g128, blk, SMEM_GEMM>>>(hb, 128, wh + OFF_M2, wl + OFF_M2, b_m2, out, 128, nullptr, 0, M, 128);
    gemm_tc<0, true, false, true><<<g128, blk, SMEM_GEMM>>>(hb + (size_t)N_NODES * 128, 128, wh + OFF_L2, wl + OFF_L2, b_l2, out + (size_t)N_NODES * 128, 128, nullptr, 0, M, 128);

    (void)in_sizes; (void)n_in; (void)out_size;
}

// round 8
// speedup vs baseline: 6.1226x; 1.0253x over previous
#include <cuda_runtime.h>
#include <cuda_fp16.h>
#include <cstdint>

#define N_NODES 50000
#define E_EDGES 800000

// ---------------- static scratch (no allocs allowed) ----------------
__device__ __half g_t256h[N_NODES * 256];
__device__ __half g_ha[N_NODES * 512];
__device__ __half g_hb[N_NODES * 512];
#define W_TOTAL 983040
__device__ __half g_wh[W_TOTAL];
__device__ __half g_wl[W_TOTAL];
// CSR scratch
__device__ int g_deg[N_NODES];
__device__ int g_off[N_NODES];
__device__ int g_cursor[N_NODES];
__device__ int g_part[64];
__device__ int g_csr_src[E_EDGES];
__device__ int g_is64;

// weight pack offsets (elements)
#define OFF_S1  0
#define OFF_S2  32768
#define OFF_S3  294912
#define OFF_S4  557056
#define OFF_CAT 819200
#define OFF_M2  950272
#define OFF_L2  966656

__device__ __forceinline__ uint32_t smem_u32(const void* p) {
    uint32_t a;
    asm("{ .reg .u64 t; cvta.to.shared.u64 t, %1; cvt.u32.u64 %0, t; }" : "=r"(a) : "l"(p));
    return a;
}
#define SW128(o) ((o) ^ (((o) >> 3) & 0x70))

// ---------------- edge-index helpers ----------------
__global__ void detect_idx_kernel(const unsigned long long* ei) {
    if (blockIdx.x == 0 && threadIdx.x == 0) {
        int ok = 1;
        #pragma unroll
        for (int i = 0; i < 16; i++)
            if (ei[i] >= (unsigned long long)N_NODES) ok = 0;
        g_is64 = ok;
    }
}
__device__ __forceinline__ void load_edge(const void* ei_raw, int e, int& s, int& d) {
    if (g_is64) {
        const long long* p = (const long long*)ei_raw;
        s = (int)__ldg(p + e); d = (int)__ldg(p + E_EDGES + e);
    } else {
        const int* p = (const int*)ei_raw;
        s = __ldg(p + e); d = __ldg(p + E_EDGES + e);
    }
}

// ---------------- CSR build ----------------
__global__ void zero_deg_kernel(int* deg) {
    int i = blockIdx.x * blockDim.x + threadIdx.x;
    if (i < N_NODES) deg[i] = 0;
}
__global__ void hist_kernel(const void* ei, int* deg) {
    int e = blockIdx.x * blockDim.x + threadIdx.x;
    if (e >= E_EDGES) return;
    int s, d; load_edge(ei, e, s, d);
    atomicAdd(&deg[d], 1);
}
#define SCAN_B 1024
__global__ void scan_block_kernel(const int* deg, int* off, int* part) {
    __shared__ int sh[SCAN_B];
    int tid = threadIdx.x;
    int i = blockIdx.x * SCAN_B + tid;
    int v = (i < N_NODES) ? deg[i] : 0;
    sh[tid] = v;
    __syncthreads();
    for (int ofs = 1; ofs < SCAN_B; ofs <<= 1) {
        int t = (tid >= ofs) ? sh[tid - ofs] : 0;
        __syncthreads();
        sh[tid] += t;
        __syncthreads();
    }
    if (i < N_NODES) off[i] = sh[tid] - v;   // exclusive
    if (tid == SCAN_B - 1) part[blockIdx.x] = sh[tid];
}
__global__ void scan_part_kernel(int* part, int nb) {
    if (threadIdx.x == 0 && blockIdx.x == 0) {
        int run = 0;
        for (int b = 0; b < nb; b++) { int t = part[b]; part[b] = run; run += t; }
    }
}
__global__ void scan_add_kernel(int* off, int* cursor, const int* part) {
    int i = blockIdx.x * SCAN_B + threadIdx.x;
    if (i < N_NODES) {
        int o = off[i] + part[blockIdx.x];
        off[i] = o;
        cursor[i] = o;
    }
}
__global__ void csr_fill_kernel(const void* ei, int* cursor, int* csr_src) {
    int e = blockIdx.x * blockDim.x + threadIdx.x;
    if (e >= E_EDGES) return;
    int s, d; load_edge(ei, e, s, d);
    int pos = atomicAdd(&cursor[d], 1);
    csr_src[pos] = s;
}

// ---------------- fused aggregations ----------------
// agg64: out = fp16(x[n] + sum_{s in N(n)} x[s]) ; one warp per node, 2 cols/lane
__global__ __launch_bounds__(256) void agg64_kernel(
    const float* __restrict__ x, const int* __restrict__ off, const int* __restrict__ deg,
    const int* __restrict__ csr, __half* __restrict__ ha)
{
    int w = (blockIdx.x * blockDim.x + threadIdx.x) >> 5;
    int lane = threadIdx.x & 31;
    if (w >= N_NODES) return;
    float2 acc0 = ((const float2*)(x + (size_t)w * 64))[lane];
    float2 acc1 = make_float2(0.f, 0.f);
    int o = off[w], dg = deg[w];
    int k = 0;
    for (; k + 2 <= dg; k += 2) {
        int s0 = __ldg(csr + o + k);
        int s1 = __ldg(csr + o + k + 1);
        float2 v0 = __ldg((const float2*)(x + (size_t)s0 * 64) + lane);
        float2 v1 = __ldg((const float2*)(x + (size_t)s1 * 64) + lane);
        acc0.x += v0.x; acc0.y += v0.y;
        acc1.x += v1.x; acc1.y += v1.y;
    }
    if (k < dg) {
        int s0 = __ldg(csr + o + k);
        float2 v0 = __ldg((const float2*)(x + (size_t)s0 * 64) + lane);
        acc0.x += v0.x; acc0.y += v0.y;
    }
    acc0.x += acc1.x; acc0.y += acc1.y;
    ((__half2*)(ha + (size_t)w * 64))[lane] = __floats2half2_rn(acc0.x, acc0.y);
}

__device__ __forceinline__ void h8_add(float* acc, uint4 v) {
    const __half2* p = (const __half2*)&v;
    #pragma unroll
    for (int i = 0; i < 4; i++) {
        float2 f = __half22float2(p[i]);
        acc[2 * i] += f.x; acc[2 * i + 1] += f.y;
    }
}

// agg256 over fp16 t256 + both head prologues.
// One warp per node; each lane owns 8 contiguous columns (one uint4 of halves).
// Lanes 0-15 cover cols 0-127 (mu head), lanes 16-31 cover cols 128-255 (logvar).
//   acc = t256[n] + sum_{s in N(n)} t256[s]   (fp32 accumulation)
//   mu  input = fp16(relu(acc[0:128]   + b_m1)) -> hh[n*128]
//   lv  input = fp16(relu(acc[128:256] + b_l1)) -> hh[N*128 + n*128]
__global__ __launch_bounds__(256) void agg256_heads_kernel(
    const __half* __restrict__ t256, const int* __restrict__ off, const int* __restrict__ deg,
    const int* __restrict__ csr, const float* __restrict__ bm1, const float* __restrict__ bl1,
    __half* __restrict__ hh)
{
    int w = (blockIdx.x * blockDim.x + threadIdx.x) >> 5;
    int lane = threadIdx.x & 31;
    if (w >= N_NODES) return;

    float acc0[8] = {}, acc1[8] = {};
    h8_add(acc0, __ldg((const uint4*)(t256 + (size_t)w * 256) + lane));

    int o = off[w], dg = deg[w];
    int k = 0;
    for (; k + 2 <= dg; k += 2) {
        int s0 = __ldg(csr + o + k);
        int s1 = __ldg(csr + o + k + 1);
        uint4 v0 = __ldg((const uint4*)(t256 + (size_t)s0 * 256) + lane);
        uint4 v1 = __ldg((const uint4*)(t256 + (size_t)s1 * 256) + lane);
        h8_add(acc0, v0);
        h8_add(acc1, v1);
    }
    if (k < dg) {
        int s0 = __ldg(csr + o + k);
        h8_add(acc0, __ldg((const uint4*)(t256 + (size_t)s0 * 256) + lane));
    }
    #pragma unroll
    for (int i = 0; i < 8; i++) acc0[i] += acc1[i];

    // bias + relu + pack; lane<16 -> mu segment, lane>=16 -> logvar segment
    const float* bias = (lane < 16) ? (bm1 + lane * 8) : (bl1 + (lane - 16) * 8);
    float4 bv0 = __ldg((const float4*)bias);
    float4 bv1 = __ldg((const float4*)bias + 1);
    float bb[8] = {bv0.x, bv0.y, bv0.z, bv0.w, bv1.x, bv1.y, bv1.z, bv1.w};

    uint4 pk;
    __half2* q = (__half2*)&pk;
    #pragma unroll
    for (int i = 0; i < 4; i++) {
        float v0 = fmaxf(acc0[2 * i]     + bb[2 * i],     0.f);
        float v1 = fmaxf(acc0[2 * i + 1] + bb[2 * i + 1], 0.f);
        q[i] = __floats2half2_rn(v0, v1);
    }
    size_t dst = (lane < 16)
        ? ((size_t)w * 128 + lane * 8)
        : ((size_t)N_NODES * 128 + (size_t)w * 128 + (lane - 16) * 8);
    *(uint4*)(hh + dst) = pk;
}

// ---------------- batched weight split: fp32 -> fp16 hi + fp16 lo ----------------
struct WSrc { const float2* p[8]; };
__global__ void split_weights_kernel(WSrc ws, __half2* __restrict__ hi, __half2* __restrict__ lo) {
    int i = blockIdx.x * blockDim.x + threadIdx.x;
    const int ends[8]   = {16384, 147456, 278528, 409600, 442368, 475136, 483328, 491520};
    const int starts[8] = {0, 16384, 147456, 278528, 409600, 442368, 475136, 483328};
    if (i >= 491520) return;
    int seg = 0;
    #pragma unroll
    for (int s = 0; s < 7; s++) if (i >= ends[s]) seg = s + 1;
    float2 v = ws.p[seg][i - starts[seg]];
    __half h0 = __float2half(v.x), h1 = __float2half(v.y);
    __half l0 = __float2half(v.x - __half2float(h0));
    __half l1 = __float2half(v.y - __half2float(h1));
    hi[i] = __halves2half2(h0, h1);
    lo[i] = __halves2half2(l0, l1);
}

// ---------------- mma.sync fp16 2-product GEMM ----------------
// C[M,Nn] = act(A[M,K] @ W[Nn,K]^T + bias); A fp16, W = Wh + Wl fp16 split.
// acc += A*Wh + A*Wl (fp32 accum). CTA tile 128x128, 8 warps of 64x32,
// K in 64-elem SW128 chunks, cp.async double buffer (2 x 48KB smem -> 2 CTA/SM).
#define GT 256
#define SMEM_GEMM 98304
#define BUFB 49152

#define LDSM4(r0, r1, r2, r3, a) \
    asm volatile("ldmatrix.sync.aligned.m8n8.x4.shared.b16 {%0,%1,%2,%3}, [%4];" \
                 : "=r"(r0), "=r"(r1), "=r"(r2), "=r"(r3) : "r"(a))

#define HMMA(c, a0, a1, a2, a3, b0, b1) \
    asm volatile("mma.sync.aligned.m16n8k16.row.col.f32.f16.f16.f32 " \
                 "{%0,%1,%2,%3}, {%4,%5,%6,%7}, {%8,%9}, {%0,%1,%2,%3};" \
                 : "+f"((c)[0]), "+f"((c)[1]), "+f"((c)[2]), "+f"((c)[3]) \
                 : "r"(a0), "r"(a1), "r"(a2), "r"(a3), "r"(b0), "r"(b1))

__device__ __forceinline__ void cp16(uint32_t saddr, const void* gptr, uint32_t sz) {
    asm volatile("cp.async.cg.shared.global [%0], [%1], 16, %2;"
                 :: "r"(saddr), "l"(gptr), "r"(sz) : "memory");
}
#define CP_COMMIT() asm volatile("cp.async.commit_group;" ::: "memory")
#define CP_WAIT(n)  asm volatile("cp.async.wait_group %0;" :: "n"(n) : "memory")

template <int ACT, bool EMITF, bool EMITH, bool HASB>
__global__ __launch_bounds__(GT, 2)
void gemm_tc(const __half* __restrict__ A, int lda,
             const __half* __restrict__ Wh, const __half* __restrict__ Wl,
             const float* __restrict__ bias,
             float* __restrict__ C, int ldc,
             __half* __restrict__ Ch, int ldch,
             int M, int K)
{
    extern __shared__ char smem[];
    const uint32_t sb = smem_u32(smem);

    const int tid = threadIdx.x;
    const int wid = tid >> 5;
    const int lane = tid & 31;
    const int m0 = blockIdx.y * 128;
    const int n0 = blockIdx.x * 128;
    const int wm = (wid & 1) * 64;
    const int wn = (wid >> 1) * 32;

    float acc[4][4][4] = {};

    const int srow = tid >> 3, sg = tid & 7;

    auto stage = [&](int buf, int k0) {
        const uint32_t tb = sb + buf * BUFB;
        #pragma unroll
        for (int t = 0; t < 4; t++) {
            const int row = srow + t * 32;
            const uint32_t so = SW128((uint32_t)(row * 128 + sg * 16));
            const int ar = m0 + row;
            const int ok = (ar < M);
            const size_t ao = (size_t)(ok ? ar : 0) * lda + k0 + sg * 8;
            cp16(tb + 0     + so, A + ao, ok ? 16 : 0);
            const size_t wo = (size_t)(n0 + row) * K + k0 + sg * 8;
            cp16(tb + 16384 + so, Wh + wo, 16);
            cp16(tb + 32768 + so, Wl + wo, 16);
        }
        CP_COMMIT();
    };

    const int o = lane >> 3, r = lane & 7;
    int aRow[4];
    #pragma unroll
    for (int i = 0; i < 4; i++) aRow[i] = (wm + 16 * i + (o & 1) * 8 + r) * 128 + (o >> 1) * 16;
    int bRow[2];
    #pragma unroll
    for (int p = 0; p < 2; p++) bRow[p] = (wn + p * 16 + (o >> 1) * 8 + r) * 128 + (o & 1) * 16;

    const int nchunks = K >> 6;
    stage(0, 0);
    for (int c = 0; c < nchunks; c++) {
        if (c + 1 < nchunks) stage((c + 1) & 1, (c + 1) << 6);
        if (c + 1 < nchunks) { CP_WAIT(1); } else { CP_WAIT(0); }
        __syncthreads();

        const uint32_t tb = sb + (c & 1) * BUFB;
        #pragma unroll
        for (int ks = 0; ks < 4; ks++) {
            const int kb = ks * 32;
            uint32_t af[4][4], wh[2][4], wl[2][4];
            #pragma unroll
            for (int i = 0; i < 4; i++) {
                const uint32_t ad = SW128((uint32_t)(aRow[i] + kb));
                LDSM4(af[i][0], af[i][1], af[i][2], af[i][3], tb + ad);
            }
            #pragma unroll
            for (int p = 0; p < 2; p++) {
                const uint32_t bd = SW128((uint32_t)(bRow[p] + kb));
                LDSM4(wh[p][0], wh[p][1], wh[p][2], wh[p][3], tb + 16384 + bd);
                LDSM4(wl[p][0], wl[p][1], wl[p][2], wl[p][3], tb + 32768 + bd);
            }
            #pragma unroll
            for (int i = 0; i < 4; i++) {
                #pragma unroll
                for (int j = 0; j < 4; j++) {
                    const uint32_t bh0 = wh[j >> 1][(j & 1) * 2], bh1 = wh[j >> 1][(j & 1) * 2 + 1];
                    const uint32_t bl0 = wl[j >> 1][(j & 1) * 2], bl1 = wl[j >> 1][(j & 1) * 2 + 1];
                    HMMA(acc[i][j], af[i][0], af[i][1], af[i][2], af[i][3], bh0, bh1);
                    HMMA(acc[i][j], af[i][0], af[i][1], af[i][2], af[i][3], bl0, bl1);
                }
            }
        }
        __syncthreads();
    }

    const int gid = lane >> 2, tig = lane & 3;
    #pragma unroll
    for (int i = 0; i < 4; i++) {
        #pragma unroll
        for (int h = 0; h < 2; h++) {
            const int row = m0 + wm + 16 * i + 8 * h + gid;
            if (row >= M) continue;
            #pragma unroll
            for (int j = 0; j < 4; j++) {
                const int col = n0 + wn + 8 * j + 2 * tig;
                float v0 = acc[i][j][2 * h], v1 = acc[i][j][2 * h + 1];
                if (HASB) { v0 += __ldg(bias + col); v1 += __ldg(bias + col + 1); }
                if (ACT == 1) { v0 = (v0 > 0.f) ? v0 : 0.1f * v0; v1 = (v1 > 0.f) ? v1 : 0.1f * v1; }
                if (ACT == 2) { v0 = fmaxf(v0, 0.f); v1 = fmaxf(v1, 0.f); }
                if (EMITF) {
                    *(float2*)&C[(size_t)row * ldc + col] = make_float2(v0, v1);
                }
                if (EMITH) {
                    *(__half2*)&Ch[(size_t)row * ldch + col] = __floats2half2_rn(v0, v1);
                }
            }
        }
    }
}

// ---------------- launch ----------------
extern "C" void kernel_launch(void* const* d_in, const int* in_sizes, int n_in,
                              void* d_out, int out_size) {
    const float* x    = (const float*)d_in[0];
    const void*  ei   = d_in[1];
    const float* W_s1 = (const float*)d_in[2];
    const float* b_s1 = (const float*)d_in[3];
    const float* W_s2 = (const float*)d_in[4];
    const float* b_s2 = (const float*)d_in[5];
    const float* W_s3 = (const float*)d_in[6];
    const float* b_s3 = (const float*)d_in[7];
    const float* W_s4 = (const float*)d_in[8];
    const float* b_s4 = (const float*)d_in[9];
    const float* W_m1 = (const float*)d_in[10];
    const float* b_m1 = (const float*)d_in[11];
    const float* W_m2 = (const float*)d_in[12];
    const float* b_m2 = (const float*)d_in[13];
    const float* W_l1 = (const float*)d_in[14];
    const float* b_l1 = (const float*)d_in[15];
    const float* W_l2 = (const float*)d_in[16];
    const float* b_l2 = (const float*)d_in[17];
    float* out = (float*)d_out;

    __half *t256h, *ha, *hb, *wh, *wl;
    int *deg, *off, *cursor, *part, *csr;
    cudaGetSymbolAddress((void**)&t256h, g_t256h);
    cudaGetSymbolAddress((void**)&ha, g_ha);
    cudaGetSymbolAddress((void**)&hb, g_hb);
    cudaGetSymbolAddress((void**)&wh, g_wh);
    cudaGetSymbolAddress((void**)&wl, g_wl);
    cudaGetSymbolAddress((void**)&deg, g_deg);
    cudaGetSymbolAddress((void**)&off, g_off);
    cudaGetSymbolAddress((void**)&cursor, g_cursor);
    cudaGetSymbolAddress((void**)&part, g_part);
    cudaGetSymbolAddress((void**)&csr, g_csr_src);

    static bool attr_done = false;
    if (!attr_done) {
        cudaFuncSetAttribute(gemm_tc<1, false, true,  true >, cudaFuncAttributeMaxDynamicSharedMemorySize, SMEM_GEMM);
        cudaFuncSetAttribute(gemm_tc<2, false, true,  true >, cudaFuncAttributeMaxDynamicSharedMemorySize, SMEM_GEMM);
        cudaFuncSetAttribute(gemm_tc<0, false, true,  false>, cudaFuncAttributeMaxDynamicSharedMemorySize, SMEM_GEMM);
        cudaFuncSetAttribute(gemm_tc<0, true,  false, true >, cudaFuncAttributeMaxDynamicSharedMemorySize, SMEM_GEMM);
        attr_done = true;
    }

    const int M = N_NODES;
    const dim3 blk(GT);
    const dim3 g512(4, (M + 127) / 128);
    const dim3 g256(2, (M + 127) / 128);
    const dim3 g128(1, (M + 127) / 128);
    const int SCAN_NB = (N_NODES + SCAN_B - 1) / SCAN_B;

    detect_idx_kernel<<<1, 32>>>((const unsigned long long*)ei);

    // ---- weight splits (one kernel for all 8 matrices) ----
    {
        WSrc ws;
        ws.p[0] = (const float2*)W_s1;
        ws.p[1] = (const float2*)W_s2;
        ws.p[2] = (const float2*)W_s3;
        ws.p[3] = (const float2*)W_s4;
        ws.p[4] = (const float2*)W_m1;
        ws.p[5] = (const float2*)W_l1;
        ws.p[6] = (const float2*)W_m2;
        ws.p[7] = (const float2*)W_l2;
        split_weights_kernel<<<(491520 + 255) / 256, 256>>>(ws, (__half2*)wh, (__half2*)wl);
    }

    // ---- CSR build ----
    zero_deg_kernel<<<(N_NODES + 255) / 256, 256>>>(deg);
    hist_kernel<<<(E_EDGES + 255) / 256, 256>>>(ei, deg);
    scan_block_kernel<<<SCAN_NB, SCAN_B>>>(deg, off, part);
    scan_part_kernel<<<1, 32>>>(part, SCAN_NB);
    scan_add_kernel<<<SCAN_NB, SCAN_B>>>(off, cursor, part);
    csr_fill_kernel<<<(E_EDGES + 255) / 256, 256>>>(ei, cursor, csr);

    // ---- agg0 = (I+A)x -> fp16 ----
    agg64_kernel<<<(N_NODES * 32 + 255) / 256, 256>>>(x, off, deg, csr, ha);

    // ---- shared MLP, fp16 activations chained through epilogues ----
    gemm_tc<1, false, true, true><<<g512, blk, SMEM_GEMM>>>(ha, 64,  wh + OFF_S1, wl + OFF_S1, b_s1, nullptr, 0, hb, 512, M, 64);
    gemm_tc<1, false, true, true><<<g512, blk, SMEM_GEMM>>>(hb, 512, wh + OFF_S2, wl + OFF_S2, b_s2, nullptr, 0, ha, 512, M, 512);
    gemm_tc<1, false, true, true><<<g512, blk, SMEM_GEMM>>>(ha, 512, wh + OFF_S3, wl + OFF_S3, b_s3, nullptr, 0, hb, 512, M, 512);
    gemm_tc<2, false, true, true><<<g512, blk, SMEM_GEMM>>>(hb, 512, wh + OFF_S4, wl + OFF_S4, b_s4, nullptr, 0, ha, 512, M, 512);

    // ---- t256 = h @ [W_m1; W_l1]^T, emitted directly as fp16 ----
    gemm_tc<0, false, true, false><<<g256, blk, SMEM_GEMM>>>(ha, 512, wh + OFF_CAT, wl + OFF_CAT, nullptr, nullptr, 0, t256h, 256, M, 512);

    // ---- agg(256) over fp16 t256 + both head prologues fused, emits fp16 head inputs ----
    agg256_heads_kernel<<<(N_NODES * 32 + 255) / 256, 256>>>(t256h, off, deg, csr, b_m1, b_l1, hb);

    // ---- heads ----
    gemm_tc<0, true, false, true><<<g128, blk, SMEM_GEMM>>>(hb, 128, wh + OFF_M2, wl + OFF_M2, b_m2, out, 128, nullptr, 0, M, 128);
    gemm_tc<0, true, false, true><<<g128, blk, SMEM_GEMM>>>(hb + (size_t)N_NODES * 128, 128, wh + OFF_L2, wl + OFF_L2, b_l2, out + (size_t)N_NODES * 128, 128, nullptr, 0, M, 128);

    (void)in_sizes; (void)n_in; (void)out_size;
}

// round 9
// speedup vs baseline: 9.3998x; 1.5353x over previous
#include <cuda_runtime.h>
#include <cuda_fp16.h>
#include <cstdint>

#define N_NODES 50000
#define E_EDGES 800000

// ---------------- static scratch (no allocs allowed) ----------------
__device__ __half g_t256h[N_NODES * 256];
__device__ __half g_ha[N_NODES * 512];
__device__ __half g_hb[N_NODES * 512];
#define W_TOTAL 983040
__device__ __half g_wh[W_TOTAL];
// CSR scratch
__device__ int g_deg[N_NODES];
__device__ int g_off[N_NODES];
__device__ int g_cursor[N_NODES];
__device__ int g_part[64];
__device__ int g_csr_src[E_EDGES];
__device__ int g_is64;

// weight pack offsets (elements)
#define OFF_S1  0
#define OFF_S2  32768
#define OFF_S3  294912
#define OFF_S4  557056
#define OFF_CAT 819200
#define OFF_M2  950272
#define OFF_L2  966656

__device__ __forceinline__ uint32_t smem_u32(const void* p) {
    uint32_t a;
    asm("{ .reg .u64 t; cvta.to.shared.u64 t, %1; cvt.u32.u64 %0, t; }" : "=r"(a) : "l"(p));
    return a;
}
#define SW128(o) ((o) ^ (((o) >> 3) & 0x70))

// ---------------- edge-index helpers ----------------
__global__ void detect_idx_kernel(const unsigned long long* ei) {
    if (blockIdx.x == 0 && threadIdx.x == 0) {
        int ok = 1;
        #pragma unroll
        for (int i = 0; i < 16; i++)
            if (ei[i] >= (unsigned long long)N_NODES) ok = 0;
        g_is64 = ok;
    }
}
__device__ __forceinline__ void load_edge(const void* ei_raw, int e, int& s, int& d) {
    if (g_is64) {
        const long long* p = (const long long*)ei_raw;
        s = (int)__ldg(p + e); d = (int)__ldg(p + E_EDGES + e);
    } else {
        const int* p = (const int*)ei_raw;
        s = __ldg(p + e); d = __ldg(p + E_EDGES + e);
    }
}

// ---------------- CSR build ----------------
__global__ void zero_deg_kernel(int* deg) {
    int i = blockIdx.x * blockDim.x + threadIdx.x;
    if (i < N_NODES) deg[i] = 0;
}
__global__ void hist_kernel(const void* ei, int* deg) {
    int e = blockIdx.x * blockDim.x + threadIdx.x;
    if (e >= E_EDGES) return;
    int s, d; load_edge(ei, e, s, d);
    atomicAdd(&deg[d], 1);
}
#define SCAN_B 1024
__global__ void scan_block_kernel(const int* deg, int* off, int* part) {
    __shared__ int sh[SCAN_B];
    int tid = threadIdx.x;
    int i = blockIdx.x * SCAN_B + tid;
    int v = (i < N_NODES) ? deg[i] : 0;
    sh[tid] = v;
    __syncthreads();
    for (int ofs = 1; ofs < SCAN_B; ofs <<= 1) {
        int t = (tid >= ofs) ? sh[tid - ofs] : 0;
        __syncthreads();
        sh[tid] += t;
        __syncthreads();
    }
    if (i < N_NODES) off[i] = sh[tid] - v;   // exclusive
    if (tid == SCAN_B - 1) part[blockIdx.x] = sh[tid];
}
__global__ void scan_part_kernel(int* part, int nb) {
    if (threadIdx.x == 0 && blockIdx.x == 0) {
        int run = 0;
        for (int b = 0; b < nb; b++) { int t = part[b]; part[b] = run; run += t; }
    }
}
__global__ void scan_add_kernel(int* off, int* cursor, const int* part) {
    int i = blockIdx.x * SCAN_B + threadIdx.x;
    if (i < N_NODES) {
        int o = off[i] + part[blockIdx.x];
        off[i] = o;
        cursor[i] = o;
    }
}
__global__ void csr_fill_kernel(const void* ei, int* cursor, int* csr_src) {
    int e = blockIdx.x * blockDim.x + threadIdx.x;
    if (e >= E_EDGES) return;
    int s, d; load_edge(ei, e, s, d);
    int pos = atomicAdd(&cursor[d], 1);
    csr_src[pos] = s;
}

// ---------------- fused aggregations ----------------
// agg64: out = fp16(x[n] + sum_{s in N(n)} x[s]) ; one warp per node, 2 cols/lane
__global__ __launch_bounds__(256) void agg64_kernel(
    const float* __restrict__ x, const int* __restrict__ off, const int* __restrict__ deg,
    const int* __restrict__ csr, __half* __restrict__ ha)
{
    int w = (blockIdx.x * blockDim.x + threadIdx.x) >> 5;
    int lane = threadIdx.x & 31;
    if (w >= N_NODES) return;
    float2 acc0 = ((const float2*)(x + (size_t)w * 64))[lane];
    float2 acc1 = make_float2(0.f, 0.f);
    int o = off[w], dg = deg[w];
    int k = 0;
    for (; k + 2 <= dg; k += 2) {
        int s0 = __ldg(csr + o + k);
        int s1 = __ldg(csr + o + k + 1);
        float2 v0 = __ldg((const float2*)(x + (size_t)s0 * 64) + lane);
        float2 v1 = __ldg((const float2*)(x + (size_t)s1 * 64) + lane);
        acc0.x += v0.x; acc0.y += v0.y;
        acc1.x += v1.x; acc1.y += v1.y;
    }
    if (k < dg) {
        int s0 = __ldg(csr + o + k);
        float2 v0 = __ldg((const float2*)(x + (size_t)s0 * 64) + lane);
        acc0.x += v0.x; acc0.y += v0.y;
    }
    acc0.x += acc1.x; acc0.y += acc1.y;
    ((__half2*)(ha + (size_t)w * 64))[lane] = __floats2half2_rn(acc0.x, acc0.y);
}

__device__ __forceinline__ void h8_add(float* acc, uint4 v) {
    const __half2* p = (const __half2*)&v;
    #pragma unroll
    for (int i = 0; i < 4; i++) {
        float2 f = __half22float2(p[i]);
        acc[2 * i] += f.x; acc[2 * i + 1] += f.y;
    }
}

// agg256 over fp16 t256 + both head prologues (see R7 comments).
__global__ __launch_bounds__(256) void agg256_heads_kernel(
    const __half* __restrict__ t256, const int* __restrict__ off, const int* __restrict__ deg,
    const int* __restrict__ csr, const float* __restrict__ bm1, const float* __restrict__ bl1,
    __half* __restrict__ hh)
{
    int w = (blockIdx.x * blockDim.x + threadIdx.x) >> 5;
    int lane = threadIdx.x & 31;
    if (w >= N_NODES) return;

    float acc0[8] = {}, acc1[8] = {};
    h8_add(acc0, __ldg((const uint4*)(t256 + (size_t)w * 256) + lane));

    int o = off[w], dg = deg[w];
    int k = 0;
    for (; k + 2 <= dg; k += 2) {
        int s0 = __ldg(csr + o + k);
        int s1 = __ldg(csr + o + k + 1);
        uint4 v0 = __ldg((const uint4*)(t256 + (size_t)s0 * 256) + lane);
        uint4 v1 = __ldg((const uint4*)(t256 + (size_t)s1 * 256) + lane);
        h8_add(acc0, v0);
        h8_add(acc1, v1);
    }
    if (k < dg) {
        int s0 = __ldg(csr + o + k);
        h8_add(acc0, __ldg((const uint4*)(t256 + (size_t)s0 * 256) + lane));
    }
    #pragma unroll
    for (int i = 0; i < 8; i++) acc0[i] += acc1[i];

    const float* bias = (lane < 16) ? (bm1 + lane * 8) : (bl1 + (lane - 16) * 8);
    float4 bv0 = __ldg((const float4*)bias);
    float4 bv1 = __ldg((const float4*)bias + 1);
    float bb[8] = {bv0.x, bv0.y, bv0.z, bv0.w, bv1.x, bv1.y, bv1.z, bv1.w};

    uint4 pk;
    __half2* q = (__half2*)&pk;
    #pragma unroll
    for (int i = 0; i < 4; i++) {
        float v0 = fmaxf(acc0[2 * i]     + bb[2 * i],     0.f);
        float v1 = fmaxf(acc0[2 * i + 1] + bb[2 * i + 1], 0.f);
        q[i] = __floats2half2_rn(v0, v1);
    }
    size_t dst = (lane < 16)
        ? ((size_t)w * 128 + lane * 8)
        : ((size_t)N_NODES * 128 + (size_t)w * 128 + (lane - 16) * 8);
    *(uint4*)(hh + dst) = pk;
}

// ---------------- batched weight convert: fp32 -> fp16 ----------------
struct WSrc { const float2* p[8]; };
__global__ void split_weights_kernel(WSrc ws, __half2* __restrict__ hi) {
    int i = blockIdx.x * blockDim.x + threadIdx.x;
    const int ends[8]   = {16384, 147456, 278528, 409600, 442368, 475136, 483328, 491520};
    const int starts[8] = {0, 16384, 147456, 278528, 409600, 442368, 475136, 483328};
    if (i >= 491520) return;
    int seg = 0;
    #pragma unroll
    for (int s = 0; s < 7; s++) if (i >= ends[s]) seg = s + 1;
    float2 v = ws.p[seg][i - starts[seg]];
    hi[i] = __halves2half2(__float2half(v.x), __float2half(v.y));
}

// ---------------- mma.sync fp16 single-product GEMM ----------------
// C[M,Nn] = act(A[M,K] @ W[Nn,K]^T + bias); A, W fp16, fp32 accum.
// CTA tile 128x128, 8 warps of 64x32, K in 64-elem SW128 chunks,
// cp.async double buffer (2 x 32KB smem -> 2 CTA/SM).
// ZSEL: blockIdx.z selects between two (A, W, bias, C) tuples (merged head GEMMs).
#define GT 256
#define SMEM_GEMM 65536
#define BUFB 32768

#define LDSM4(r0, r1, r2, r3, a) \
    asm volatile("ldmatrix.sync.aligned.m8n8.x4.shared.b16 {%0,%1,%2,%3}, [%4];" \
                 : "=r"(r0), "=r"(r1), "=r"(r2), "=r"(r3) : "r"(a))

#define HMMA(c, a0, a1, a2, a3, b0, b1) \
    asm volatile("mma.sync.aligned.m16n8k16.row.col.f32.f16.f16.f32 " \
                 "{%0,%1,%2,%3}, {%4,%5,%6,%7}, {%8,%9}, {%0,%1,%2,%3};" \
                 : "+f"((c)[0]), "+f"((c)[1]), "+f"((c)[2]), "+f"((c)[3]) \
                 : "r"(a0), "r"(a1), "r"(a2), "r"(a3), "r"(b0), "r"(b1))

__device__ __forceinline__ void cp16(uint32_t saddr, const void* gptr, uint32_t sz) {
    asm volatile("cp.async.cg.shared.global [%0], [%1], 16, %2;"
                 :: "r"(saddr), "l"(gptr), "r"(sz) : "memory");
}
#define CP_COMMIT() asm volatile("cp.async.commit_group;" ::: "memory")
#define CP_WAIT(n)  asm volatile("cp.async.wait_group %0;" :: "n"(n) : "memory")

template <int ACT, bool EMITF, bool EMITH, bool HASB, bool ZSEL>
__global__ __launch_bounds__(GT, 2)
void gemm_tc(const __half* __restrict__ A, const __half* __restrict__ A2, int lda,
             const __half* __restrict__ W, const __half* __restrict__ W2,
             const float* __restrict__ bias, const float* __restrict__ bias2,
             float* __restrict__ C, float* __restrict__ C2, int ldc,
             __half* __restrict__ Ch, int ldch,
             int M, int K)
{
    extern __shared__ char smem[];
    const uint32_t sb = smem_u32(smem);

    if (ZSEL && blockIdx.z) { A = A2; W = W2; bias = bias2; C = C2; }

    const int tid = threadIdx.x;
    const int wid = tid >> 5;
    const int lane = tid & 31;
    const int m0 = blockIdx.y * 128;
    const int n0 = blockIdx.x * 128;
    const int wm = (wid & 1) * 64;
    const int wn = (wid >> 1) * 32;

    float acc[4][4][4] = {};

    const int srow = tid >> 3, sg = tid & 7;

    auto stage = [&](int buf, int k0) {
        const uint32_t tb = sb + buf * BUFB;
        #pragma unroll
        for (int t = 0; t < 4; t++) {
            const int row = srow + t * 32;
            const uint32_t so = SW128((uint32_t)(row * 128 + sg * 16));
            const int ar = m0 + row;
            const int ok = (ar < M);
            const size_t ao = (size_t)(ok ? ar : 0) * lda + k0 + sg * 8;
            cp16(tb + 0     + so, A + ao, ok ? 16 : 0);
            const size_t wo = (size_t)(n0 + row) * K + k0 + sg * 8;
            cp16(tb + 16384 + so, W + wo, 16);
        }
        CP_COMMIT();
    };

    const int o = lane >> 3, r = lane & 7;
    int aRow[4];
    #pragma unroll
    for (int i = 0; i < 4; i++) aRow[i] = (wm + 16 * i + (o & 1) * 8 + r) * 128 + (o >> 1) * 16;
    int bRow[2];
    #pragma unroll
    for (int p = 0; p < 2; p++) bRow[p] = (wn + p * 16 + (o >> 1) * 8 + r) * 128 + (o & 1) * 16;

    const int nchunks = K >> 6;
    stage(0, 0);
    for (int c = 0; c < nchunks; c++) {
        if (c + 1 < nchunks) stage((c + 1) & 1, (c + 1) << 6);
        if (c + 1 < nchunks) { CP_WAIT(1); } else { CP_WAIT(0); }
        __syncthreads();

        const uint32_t tb = sb + (c & 1) * BUFB;
        #pragma unroll
        for (int ks = 0; ks < 4; ks++) {
            const int kb = ks * 32;
            uint32_t af[4][4], wf[2][4];
            #pragma unroll
            for (int i = 0; i < 4; i++) {
                const uint32_t ad = SW128((uint32_t)(aRow[i] + kb));
                LDSM4(af[i][0], af[i][1], af[i][2], af[i][3], tb + ad);
            }
            #pragma unroll
            for (int p = 0; p < 2; p++) {
                const uint32_t bd = SW128((uint32_t)(bRow[p] + kb));
                LDSM4(wf[p][0], wf[p][1], wf[p][2], wf[p][3], tb + 16384 + bd);
            }
            #pragma unroll
            for (int i = 0; i < 4; i++) {
                #pragma unroll
                for (int j = 0; j < 4; j++) {
                    HMMA(acc[i][j], af[i][0], af[i][1], af[i][2], af[i][3],
                         wf[j >> 1][(j & 1) * 2], wf[j >> 1][(j & 1) * 2 + 1]);
                }
            }
        }
        __syncthreads();
    }

    const int gid = lane >> 2, tig = lane & 3;
    #pragma unroll
    for (int i = 0; i < 4; i++) {
        #pragma unroll
        for (int h = 0; h < 2; h++) {
            const int row = m0 + wm + 16 * i + 8 * h + gid;
            if (row >= M) continue;
            #pragma unroll
            for (int j = 0; j < 4; j++) {
                const int col = n0 + wn + 8 * j + 2 * tig;
                float v0 = acc[i][j][2 * h], v1 = acc[i][j][2 * h + 1];
                if (HASB) { v0 += __ldg(bias + col); v1 += __ldg(bias + col + 1); }
                if (ACT == 1) { v0 = (v0 > 0.f) ? v0 : 0.1f * v0; v1 = (v1 > 0.f) ? v1 : 0.1f * v1; }
                if (ACT == 2) { v0 = fmaxf(v0, 0.f); v1 = fmaxf(v1, 0.f); }
                if (EMITF) {
                    *(float2*)&C[(size_t)row * ldc + col] = make_float2(v0, v1);
                }
                if (EMITH) {
                    *(__half2*)&Ch[(size_t)row * ldch + col] = __floats2half2_rn(v0, v1);
                }
            }
        }
    }
}

// ---------------- launch ----------------
extern "C" void kernel_launch(void* const* d_in, const int* in_sizes, int n_in,
                              void* d_out, int out_size) {
    const float* x    = (const float*)d_in[0];
    const void*  ei   = d_in[1];
    const float* W_s1 = (const float*)d_in[2];
    const float* b_s1 = (const float*)d_in[3];
    const float* W_s2 = (const float*)d_in[4];
    const float* b_s2 = (const float*)d_in[5];
    const float* W_s3 = (const float*)d_in[6];
    const float* b_s3 = (const float*)d_in[7];
    const float* W_s4 = (const float*)d_in[8];
    const float* b_s4 = (const float*)d_in[9];
    const float* W_m1 = (const float*)d_in[10];
    const float* b_m1 = (const float*)d_in[11];
    const float* W_m2 = (const float*)d_in[12];
    const float* b_m2 = (const float*)d_in[13];
    const float* W_l1 = (const float*)d_in[14];
    const float* b_l1 = (const float*)d_in[15];
    const float* W_l2 = (const float*)d_in[16];
    const float* b_l2 = (const float*)d_in[17];
    float* out = (float*)d_out;

    __half *t256h, *ha, *hb, *wh;
    int *deg, *off, *cursor, *part, *csr;
    cudaGetSymbolAddress((void**)&t256h, g_t256h);
    cudaGetSymbolAddress((void**)&ha, g_ha);
    cudaGetSymbolAddress((void**)&hb, g_hb);
    cudaGetSymbolAddress((void**)&wh, g_wh);
    cudaGetSymbolAddress((void**)&deg, g_deg);
    cudaGetSymbolAddress((void**)&off, g_off);
    cudaGetSymbolAddress((void**)&cursor, g_cursor);
    cudaGetSymbolAddress((void**)&part, g_part);
    cudaGetSymbolAddress((void**)&csr, g_csr_src);

    static bool attr_done = false;
    if (!attr_done) {
        cudaFuncSetAttribute(gemm_tc<1, false, true,  true,  false>, cudaFuncAttributeMaxDynamicSharedMemorySize, SMEM_GEMM);
        cudaFuncSetAttribute(gemm_tc<2, false, true,  true,  false>, cudaFuncAttributeMaxDynamicSharedMemorySize, SMEM_GEMM);
        cudaFuncSetAttribute(gemm_tc<0, false, true,  false, false>, cudaFuncAttributeMaxDynamicSharedMemorySize, SMEM_GEMM);
        cudaFuncSetAttribute(gemm_tc<0, true,  false, true,  true >, cudaFuncAttributeMaxDynamicSharedMemorySize, SMEM_GEMM);
        attr_done = true;
    }

    const int M = N_NODES;
    const dim3 blk(GT);
    const dim3 g512(4, (M + 127) / 128);
    const dim3 g256(2, (M + 127) / 128);
    const dim3 gheads(1, (M + 127) / 128, 2);
    const int SCAN_NB = (N_NODES + SCAN_B - 1) / SCAN_B;

    detect_idx_kernel<<<1, 32>>>((const unsigned long long*)ei);

    // ---- weight convert (one kernel for all 8 matrices) ----
    {
        WSrc ws;
        ws.p[0] = (const float2*)W_s1;
        ws.p[1] = (const float2*)W_s2;
        ws.p[2] = (const float2*)W_s3;
        ws.p[3] = (const float2*)W_s4;
        ws.p[4] = (const float2*)W_m1;
        ws.p[5] = (const float2*)W_l1;
        ws.p[6] = (const float2*)W_m2;
        ws.p[7] = (const float2*)W_l2;
        split_weights_kernel<<<(491520 + 255) / 256, 256>>>(ws, (__half2*)wh);
    }

    // ---- CSR build ----
    zero_deg_kernel<<<(N_NODES + 255) / 256, 256>>>(deg);
    hist_kernel<<<(E_EDGES + 255) / 256, 256>>>(ei, deg);
    scan_block_kernel<<<SCAN_NB, SCAN_B>>>(deg, off, part);
    scan_part_kernel<<<1, 32>>>(part, SCAN_NB);
    scan_add_kernel<<<SCAN_NB, SCAN_B>>>(off, cursor, part);
    csr_fill_kernel<<<(E_EDGES + 255) / 256, 256>>>(ei, cursor, csr);

    // ---- agg0 = (I+A)x -> fp16 ----
    agg64_kernel<<<(N_NODES * 32 + 255) / 256, 256>>>(x, off, deg, csr, ha);

    // ---- shared MLP, fp16 activations chained through epilogues ----
    gemm_tc<1, false, true, true, false><<<g512, blk, SMEM_GEMM>>>(ha, nullptr, 64,  wh + OFF_S1, nullptr, b_s1, nullptr, nullptr, nullptr, 0, hb, 512, M, 64);
    gemm_tc<1, false, true, true, false><<<g512, blk, SMEM_GEMM>>>(hb, nullptr, 512, wh + OFF_S2, nullptr, b_s2, nullptr, nullptr, nullptr, 0, ha, 512, M, 512);
    gemm_tc<1, false, true, true, false><<<g512, blk, SMEM_GEMM>>>(ha, nullptr, 512, wh + OFF_S3, nullptr, b_s3, nullptr, nullptr, nullptr, 0, hb, 512, M, 512);
    gemm_tc<2, false, true, true, false><<<g512, blk, SMEM_GEMM>>>(hb, nullptr, 512, wh + OFF_S4, nullptr, b_s4, nullptr, nullptr, nullptr, 0, ha, 512, M, 512);

    // ---- t256 = h @ [W_m1; W_l1]^T, emitted directly as fp16 ----
    gemm_tc<0, false, true, false, false><<<g256, blk, SMEM_GEMM>>>(ha, nullptr, 512, wh + OFF_CAT, nullptr, nullptr, nullptr, nullptr, nullptr, 0, t256h, 256, M, 512);

    // ---- agg(256) over fp16 t256 + both head prologues fused ----
    agg256_heads_kernel<<<(N_NODES * 32 + 255) / 256, 256>>>(t256h, off, deg, csr, b_m1, b_l1, hb);

    // ---- both heads in ONE launch (blockIdx.z selects head) ----
    gemm_tc<0, true, false, true, true><<<gheads, blk, SMEM_GEMM>>>(
        hb, hb + (size_t)N_NODES * 128, 128,
        wh + OFF_M2, wh + OFF_L2,
        b_m2, b_l2,
        out, out + (size_t)N_NODES * 128, 128,
        nullptr, 0, M, 128);

    (void)in_sizes; (void)n_in; (void)out_size;
}

// round 10
// speedup vs baseline: 9.4825x; 1.0088x over previous
#include <cuda_runtime.h>
#include <cuda_fp16.h>
#include <cstdint>

#define N_NODES 50000
#define E_EDGES 800000

// ---------------- static scratch (no allocs allowed) ----------------
__device__ __half g_t256h[N_NODES * 256];
__device__ __half g_ha[N_NODES * 512];
__device__ __half g_hb[N_NODES * 512];
#define W_TOTAL 983040
__device__ __half g_wh[W_TOTAL];
// CSR scratch
__device__ int g_deg[N_NODES];
__device__ int g_off[N_NODES];
__device__ int g_cursor[N_NODES];
__device__ int g_csr_src[E_EDGES];
__device__ int g_base;
__device__ int g_is64;

// weight pack offsets (elements)
#define OFF_S1  0
#define OFF_S2  32768
#define OFF_S3  294912
#define OFF_S4  557056
#define OFF_CAT 819200
#define OFF_M2  950272
#define OFF_L2  966656

__device__ __forceinline__ uint32_t smem_u32(const void* p) {
    uint32_t a;
    asm("{ .reg .u64 t; cvta.to.shared.u64 t, %1; cvt.u32.u64 %0, t; }" : "=r"(a) : "l"(p));
    return a;
}
#define SW128(o) ((o) ^ (((o) >> 3) & 0x70))

// ---------------- edge-index helpers ----------------
__global__ void detect_idx_kernel(const unsigned long long* ei) {
    if (blockIdx.x == 0 && threadIdx.x == 0) {
        int ok = 1;
        #pragma unroll
        for (int i = 0; i < 16; i++)
            if (ei[i] >= (unsigned long long)N_NODES) ok = 0;
        g_is64 = ok;
        g_base = 0;
    }
}
__device__ __forceinline__ void load_edge(const void* ei_raw, int e, int& s, int& d) {
    if (g_is64) {
        const long long* p = (const long long*)ei_raw;
        s = (int)__ldg(p + e); d = (int)__ldg(p + E_EDGES + e);
    } else {
        const int* p = (const int*)ei_raw;
        s = __ldg(p + e); d = __ldg(p + E_EDGES + e);
    }
}

// ---------------- CSR build ----------------
// hist: dst-only, two edges per thread (coalesced paired loads)
__global__ void hist_kernel(const void* ei, int* deg) {
    int t = blockIdx.x * blockDim.x + threadIdx.x;
    if (t >= E_EDGES / 2) return;
    if (g_is64) {
        const longlong2* p = (const longlong2*)((const long long*)ei + E_EDGES);
        longlong2 v = __ldg(p + t);
        atomicAdd(&deg[(int)v.x], 1);
        atomicAdd(&deg[(int)v.y], 1);
    } else {
        const int2* p = (const int2*)((const int*)ei + E_EDGES);
        int2 v = __ldg(p + t);
        atomicAdd(&deg[v.x], 1);
        atomicAdd(&deg[v.y], 1);
    }
}
// fused scan: block-local prefix + atomic region claim.
// CSR node-segment order in memory is arbitrary (only per-node contiguity
// matters), so blocks may claim disjoint regions in arrival order.
#define SCAN_B 1024
__global__ void scan_fused_kernel(const int* __restrict__ deg, int* __restrict__ off,
                                  int* __restrict__ cursor, int* __restrict__ gbase) {
    __shared__ int sh[SCAN_B];
    __shared__ int base;
    int tid = threadIdx.x;
    int i = blockIdx.x * SCAN_B + tid;
    int v = (i < N_NODES) ? deg[i] : 0;
    sh[tid] = v;
    __syncthreads();
    for (int ofs = 1; ofs < SCAN_B; ofs <<= 1) {
        int t = (tid >= ofs) ? sh[tid - ofs] : 0;
        __syncthreads();
        sh[tid] += t;
        __syncthreads();
    }
    if (tid == SCAN_B - 1) base = atomicAdd(gbase, sh[tid]);
    __syncthreads();
    if (i < N_NODES) {
        int o = base + sh[tid] - v;
        off[i] = o;
        cursor[i] = o;
    }
}
__global__ void csr_fill_kernel(const void* ei, int* cursor, int* csr_src) {
    int e = blockIdx.x * blockDim.x + threadIdx.x;
    if (e >= E_EDGES) return;
    int s, d; load_edge(ei, e, s, d);
    int pos = atomicAdd(&cursor[d], 1);
    csr_src[pos] = s;
}

// ---------------- fused aggregations ----------------
// agg64: out = fp16(x[n] + sum_{s in N(n)} x[s]) ; one warp per node, 2 cols/lane
__global__ __launch_bounds__(256) void agg64_kernel(
    const float* __restrict__ x, const int* __restrict__ off, const int* __restrict__ deg,
    const int* __restrict__ csr, __half* __restrict__ ha)
{
    int w = (blockIdx.x * blockDim.x + threadIdx.x) >> 5;
    int lane = threadIdx.x & 31;
    if (w >= N_NODES) return;
    float2 acc0 = ((const float2*)(x + (size_t)w * 64))[lane];
    float2 acc1 = make_float2(0.f, 0.f);
    int o = off[w], dg = deg[w];
    int k = 0;
    for (; k + 2 <= dg; k += 2) {
        int s0 = __ldg(csr + o + k);
        int s1 = __ldg(csr + o + k + 1);
        float2 v0 = __ldg((const float2*)(x + (size_t)s0 * 64) + lane);
        float2 v1 = __ldg((const float2*)(x + (size_t)s1 * 64) + lane);
        acc0.x += v0.x; acc0.y += v0.y;
        acc1.x += v1.x; acc1.y += v1.y;
    }
    if (k < dg) {
        int s0 = __ldg(csr + o + k);
        float2 v0 = __ldg((const float2*)(x + (size_t)s0 * 64) + lane);
        acc0.x += v0.x; acc0.y += v0.y;
    }
    acc0.x += acc1.x; acc0.y += acc1.y;
    ((__half2*)(ha + (size_t)w * 64))[lane] = __floats2half2_rn(acc0.x, acc0.y);
}

__device__ __forceinline__ void h8_add(float* acc, uint4 v) {
    const __half2* p = (const __half2*)&v;
    #pragma unroll
    for (int i = 0; i < 4; i++) {
        float2 f = __half22float2(p[i]);
        acc[2 * i] += f.x; acc[2 * i + 1] += f.y;
    }
}

// agg256 over fp16 t256 + both head prologues.
__global__ __launch_bounds__(256) void agg256_heads_kernel(
    const __half* __restrict__ t256, const int* __restrict__ off, const int* __restrict__ deg,
    const int* __restrict__ csr, const float* __restrict__ bm1, const float* __restrict__ bl1,
    __half* __restrict__ hh)
{
    int w = (blockIdx.x * blockDim.x + threadIdx.x) >> 5;
    int lane = threadIdx.x & 31;
    if (w >= N_NODES) return;

    float acc0[8] = {}, acc1[8] = {};
    h8_add(acc0, __ldg((const uint4*)(t256 + (size_t)w * 256) + lane));

    int o = off[w], dg = deg[w];
    int k = 0;
    for (; k + 2 <= dg; k += 2) {
        int s0 = __ldg(csr + o + k);
        int s1 = __ldg(csr + o + k + 1);
        uint4 v0 = __ldg((const uint4*)(t256 + (size_t)s0 * 256) + lane);
        uint4 v1 = __ldg((const uint4*)(t256 + (size_t)s1 * 256) + lane);
        h8_add(acc0, v0);
        h8_add(acc1, v1);
    }
    if (k < dg) {
        int s0 = __ldg(csr + o + k);
        h8_add(acc0, __ldg((const uint4*)(t256 + (size_t)s0 * 256) + lane));
    }
    #pragma unroll
    for (int i = 0; i < 8; i++) acc0[i] += acc1[i];

    const float* bias = (lane < 16) ? (bm1 + lane * 8) : (bl1 + (lane - 16) * 8);
    float4 bv0 = __ldg((const float4*)bias);
    float4 bv1 = __ldg((const float4*)bias + 1);
    float bb[8] = {bv0.x, bv0.y, bv0.z, bv0.w, bv1.x, bv1.y, bv1.z, bv1.w};

    uint4 pk;
    __half2* q = (__half2*)&pk;
    #pragma unroll
    for (int i = 0; i < 4; i++) {
        float v0 = fmaxf(acc0[2 * i]     + bb[2 * i],     0.f);
        float v1 = fmaxf(acc0[2 * i + 1] + bb[2 * i + 1], 0.f);
        q[i] = __floats2half2_rn(v0, v1);
    }
    size_t dst = (lane < 16)
        ? ((size_t)w * 128 + lane * 8)
        : ((size_t)N_NODES * 128 + (size_t)w * 128 + (lane - 16) * 8);
    *(uint4*)(hh + dst) = pk;
}

// ---------------- batched weight convert: fp32 -> fp16 ----------------
struct WSrc { const float2* p[8]; };
__global__ void split_weights_kernel(WSrc ws, __half2* __restrict__ hi) {
    int i = blockIdx.x * blockDim.x + threadIdx.x;
    const int ends[8]   = {16384, 147456, 278528, 409600, 442368, 475136, 483328, 491520};
    const int starts[8] = {0, 16384, 147456, 278528, 409600, 442368, 475136, 483328};
    if (i >= 491520) return;
    int seg = 0;
    #pragma unroll
    for (int s = 0; s < 7; s++) if (i >= ends[s]) seg = s + 1;
    float2 v = ws.p[seg][i - starts[seg]];
    hi[i] = __halves2half2(__float2half(v.x), __float2half(v.y));
}

// ---------------- mma.sync fp16 single-product GEMM ----------------
#define GT 256
#define SMEM_GEMM 65536
#define BUFB 32768

#define LDSM4(r0, r1, r2, r3, a) \
    asm volatile("ldmatrix.sync.aligned.m8n8.x4.shared.b16 {%0,%1,%2,%3}, [%4];" \
                 : "=r"(r0), "=r"(r1), "=r"(r2), "=r"(r3) : "r"(a))

#define HMMA(c, a0, a1, a2, a3, b0, b1) \
    asm volatile("mma.sync.aligned.m16n8k16.row.col.f32.f16.f16.f32 " \
                 "{%0,%1,%2,%3}, {%4,%5,%6,%7}, {%8,%9}, {%0,%1,%2,%3};" \
                 : "+f"((c)[0]), "+f"((c)[1]), "+f"((c)[2]), "+f"((c)[3]) \
                 : "r"(a0), "r"(a1), "r"(a2), "r"(a3), "r"(b0), "r"(b1))

__device__ __forceinline__ void cp16(uint32_t saddr, const void* gptr, uint32_t sz) {
    asm volatile("cp.async.cg.shared.global [%0], [%1], 16, %2;"
                 :: "r"(saddr), "l"(gptr), "r"(sz) : "memory");
}
#define CP_COMMIT() asm volatile("cp.async.commit_group;" ::: "memory")
#define CP_WAIT(n)  asm volatile("cp.async.wait_group %0;" :: "n"(n) : "memory")

template <int ACT, bool EMITF, bool EMITH, bool HASB, bool ZSEL>
__global__ __launch_bounds__(GT, 2)
void gemm_tc(const __half* __restrict__ A, const __half* __restrict__ A2, int lda,
             const __half* __restrict__ W, const __half* __restrict__ W2,
             const float* __restrict__ bias, const float* __restrict__ bias2,
             float* __restrict__ C, float* __restrict__ C2, int ldc,
             __half* __restrict__ Ch, int ldch,
             int M, int K)
{
    extern __shared__ char smem[];
    const uint32_t sb = smem_u32(smem);

    if (ZSEL && blockIdx.z) { A = A2; W = W2; bias = bias2; C = C2; }

    const int tid = threadIdx.x;
    const int wid = tid >> 5;
    const int lane = tid & 31;
    const int m0 = blockIdx.y * 128;
    const int n0 = blockIdx.x * 128;
    const int wm = (wid & 1) * 64;
    const int wn = (wid >> 1) * 32;

    float acc[4][4][4] = {};

    const int srow = tid >> 3, sg = tid & 7;

    auto stage = [&](int buf, int k0) {
        const uint32_t tb = sb + buf * BUFB;
        #pragma unroll
        for (int t = 0; t < 4; t++) {
            const int row = srow + t * 32;
            const uint32_t so = SW128((uint32_t)(row * 128 + sg * 16));
            const int ar = m0 + row;
            const int ok = (ar < M);
            const size_t ao = (size_t)(ok ? ar : 0) * lda + k0 + sg * 8;
            cp16(tb + 0     + so, A + ao, ok ? 16 : 0);
            const size_t wo = (size_t)(n0 + row) * K + k0 + sg * 8;
            cp16(tb + 16384 + so, W + wo, 16);
        }
        CP_COMMIT();
    };

    const int o = lane >> 3, r = lane & 7;
    int aRow[4];
    #pragma unroll
    for (int i = 0; i < 4; i++) aRow[i] = (wm + 16 * i + (o & 1) * 8 + r) * 128 + (o >> 1) * 16;
    int bRow[2];
    #pragma unroll
    for (int p = 0; p < 2; p++) bRow[p] = (wn + p * 16 + (o >> 1) * 8 + r) * 128 + (o & 1) * 16;

    const int nchunks = K >> 6;
    stage(0, 0);
    for (int c = 0; c < nchunks; c++) {
        if (c + 1 < nchunks) stage((c + 1) & 1, (c + 1) << 6);
        if (c + 1 < nchunks) { CP_WAIT(1); } else { CP_WAIT(0); }
        __syncthreads();

        const uint32_t tb = sb + (c & 1) * BUFB;
        #pragma unroll
        for (int ks = 0; ks < 4; ks++) {
            const int kb = ks * 32;
            uint32_t af[4][4], wf[2][4];
            #pragma unroll
            for (int i = 0; i < 4; i++) {
                const uint32_t ad = SW128((uint32_t)(aRow[i] + kb));
                LDSM4(af[i][0], af[i][1], af[i][2], af[i][3], tb + ad);
            }
            #pragma unroll
            for (int p = 0; p < 2; p++) {
                const uint32_t bd = SW128((uint32_t)(bRow[p] + kb));
                LDSM4(wf[p][0], wf[p][1], wf[p][2], wf[p][3], tb + 16384 + bd);
            }
            #pragma unroll
            for (int i = 0; i < 4; i++) {
                #pragma unroll
                for (int j = 0; j < 4; j++) {
                    HMMA(acc[i][j], af[i][0], af[i][1], af[i][2], af[i][3],
                         wf[j >> 1][(j & 1) * 2], wf[j >> 1][(j & 1) * 2 + 1]);
                }
            }
        }
        __syncthreads();
    }

    const int gid = lane >> 2, tig = lane & 3;
    #pragma unroll
    for (int i = 0; i < 4; i++) {
        #pragma unroll
        for (int h = 0; h < 2; h++) {
            const int row = m0 + wm + 16 * i + 8 * h + gid;
            if (row >= M) continue;
            #pragma unroll
            for (int j = 0; j < 4; j++) {
                const int col = n0 + wn + 8 * j + 2 * tig;
                float v0 = acc[i][j][2 * h], v1 = acc[i][j][2 * h + 1];
                if (HASB) { v0 += __ldg(bias + col); v1 += __ldg(bias + col + 1); }
                if (ACT == 1) { v0 = (v0 > 0.f) ? v0 : 0.1f * v0; v1 = (v1 > 0.f) ? v1 : 0.1f * v1; }
                if (ACT == 2) { v0 = fmaxf(v0, 0.f); v1 = fmaxf(v1, 0.f); }
                if (EMITF) {
                    *(float2*)&C[(size_t)row * ldc + col] = make_float2(v0, v1);
                }
                if (EMITH) {
                    *(__half2*)&Ch[(size_t)row * ldch + col] = __floats2half2_rn(v0, v1);
                }
            }
        }
    }
}

// ---------------- launch ----------------
extern "C" void kernel_launch(void* const* d_in, const int* in_sizes, int n_in,
                              void* d_out, int out_size) {
    const float* x    = (const float*)d_in[0];
    const void*  ei   = d_in[1];
    const float* W_s1 = (const float*)d_in[2];
    const float* b_s1 = (const float*)d_in[3];
    const float* W_s2 = (const float*)d_in[4];
    const float* b_s2 = (const float*)d_in[5];
    const float* W_s3 = (const float*)d_in[6];
    const float* b_s3 = (const float*)d_in[7];
    const float* W_s4 = (const float*)d_in[8];
    const float* b_s4 = (const float*)d_in[9];
    const float* W_m1 = (const float*)d_in[10];
    const float* b_m1 = (const float*)d_in[11];
    const float* W_m2 = (const float*)d_in[12];
    const float* b_m2 = (const float*)d_in[13];
    const float* W_l1 = (const float*)d_in[14];
    const float* b_l1 = (const float*)d_in[15];
    const float* W_l2 = (const float*)d_in[16];
    const float* b_l2 = (const float*)d_in[17];
    float* out = (float*)d_out;

    __half *t256h, *ha, *hb, *wh;
    int *deg, *off, *cursor, *csr, *gbase;
    cudaGetSymbolAddress((void**)&t256h, g_t256h);
    cudaGetSymbolAddress((void**)&ha, g_ha);
    cudaGetSymbolAddress((void**)&hb, g_hb);
    cudaGetSymbolAddress((void**)&wh, g_wh);
    cudaGetSymbolAddress((void**)&deg, g_deg);
    cudaGetSymbolAddress((void**)&off, g_off);
    cudaGetSymbolAddress((void**)&cursor, g_cursor);
    cudaGetSymbolAddress((void**)&csr, g_csr_src);
    cudaGetSymbolAddress((void**)&gbase, g_base);

    static bool init_done = false;
    static cudaStream_t s_side = nullptr;
    static cudaEvent_t ev_fork = nullptr, ev_join = nullptr;
    if (!init_done) {
        cudaFuncSetAttribute(gemm_tc<1, false, true,  true,  false>, cudaFuncAttributeMaxDynamicSharedMemorySize, SMEM_GEMM);
        cudaFuncSetAttribute(gemm_tc<2, false, true,  true,  false>, cudaFuncAttributeMaxDynamicSharedMemorySize, SMEM_GEMM);
        cudaFuncSetAttribute(gemm_tc<0, false, true,  false, false>, cudaFuncAttributeMaxDynamicSharedMemorySize, SMEM_GEMM);
        cudaFuncSetAttribute(gemm_tc<0, true,  false, true,  true >, cudaFuncAttributeMaxDynamicSharedMemorySize, SMEM_GEMM);
        cudaStreamCreateWithFlags(&s_side, cudaStreamNonBlocking);
        cudaEventCreateWithFlags(&ev_fork, cudaEventDisableTiming);
        cudaEventCreateWithFlags(&ev_join, cudaEventDisableTiming);
        init_done = true;
    }

    const int M = N_NODES;
    const dim3 blk(GT);
    const dim3 g512(4, (M + 127) / 128);
    const dim3 g256(2, (M + 127) / 128);
    const dim3 gheads(1, (M + 127) / 128, 2);
    const int SCAN_NB = (N_NODES + SCAN_B - 1) / SCAN_B;

    // ---- fork: weight convert on side stream, overlapped with CSR build ----
    cudaEventRecord(ev_fork, 0);
    cudaStreamWaitEvent(s_side, ev_fork, 0);
    {
        WSrc ws;
        ws.p[0] = (const float2*)W_s1;
        ws.p[1] = (const float2*)W_s2;
        ws.p[2] = (const float2*)W_s3;
        ws.p[3] = (const float2*)W_s4;
        ws.p[4] = (const float2*)W_m1;
        ws.p[5] = (const float2*)W_l1;
        ws.p[6] = (const float2*)W_m2;
        ws.p[7] = (const float2*)W_l2;
        split_weights_kernel<<<(491520 + 255) / 256, 256, 0, s_side>>>(ws, (__half2*)wh);
    }
    cudaEventRecord(ev_join, s_side);

    // ---- main stream: CSR build ----
    detect_idx_kernel<<<1, 32>>>((const unsigned long long*)ei);
    cudaMemsetAsync(deg, 0, N_NODES * sizeof(int), 0);
    hist_kernel<<<(E_EDGES / 2 + 255) / 256, 256>>>(ei, deg);
    scan_fused_kernel<<<SCAN_NB, SCAN_B>>>(deg, off, cursor, gbase);
    csr_fill_kernel<<<(E_EDGES + 255) / 256, 256>>>(ei, cursor, csr);

    // ---- agg0 = (I+A)x -> fp16 ----
    agg64_kernel<<<(N_NODES * 32 + 255) / 256, 256>>>(x, off, deg, csr, ha);

    // ---- join: weights ready before s1 ----
    cudaStreamWaitEvent(0, ev_join, 0);

    // ---- shared MLP, fp16 activations chained through epilogues ----
    gemm_tc<1, false, true, true, false><<<g512, blk, SMEM_GEMM>>>(ha, nullptr, 64,  wh + OFF_S1, nullptr, b_s1, nullptr, nullptr, nullptr, 0, hb, 512, M, 64);
    gemm_tc<1, false, true, true, false><<<g512, blk, SMEM_GEMM>>>(hb, nullptr, 512, wh + OFF_S2, nullptr, b_s2, nullptr, nullptr, nullptr, 0, ha, 512, M, 512);
    gemm_tc<1, false, true, true, false><<<g512, blk, SMEM_GEMM>>>(ha, nullptr, 512, wh + OFF_S3, nullptr, b_s3, nullptr, nullptr, nullptr, 0, hb, 512, M, 512);
    gemm_tc<2, false, true, true, false><<<g512, blk, SMEM_GEMM>>>(hb, nullptr, 512, wh + OFF_S4, nullptr, b_s4, nullptr, nullptr, nullptr, 0, ha, 512, M, 512);

    // ---- t256 = h @ [W_m1; W_l1]^T, emitted directly as fp16 ----
    gemm_tc<0, false, true, false, false><<<g256, blk, SMEM_GEMM>>>(ha, nullptr, 512, wh + OFF_CAT, nullptr, nullptr, nullptr, nullptr, nullptr, 0, t256h, 256, M, 512);

    // ---- agg(256) over fp16 t256 + both head prologues fused ----
    agg256_heads_kernel<<<(N_NODES * 32 + 255) / 256, 256>>>(t256h, off, deg, csr, b_m1, b_l1, hb);

    // ---- both heads in ONE launch (blockIdx.z selects head) ----
    gemm_tc<0, true, false, true, true><<<gheads, blk, SMEM_GEMM>>>(
        hb, hb + (size_t)N_NODES * 128, 128,
        wh + OFF_M2, wh + OFF_L2,
        b_m2, b_l2,
        out, out + (size_t)N_NODES * 128, 128,
        nullptr, 0, M, 128);

    (void)in_sizes; (void)n_in; (void)out_size;
}